// round 7
// baseline (speedup 1.0000x reference)
#include <cuda_runtime.h>
#include <math.h>
#include <stdint.h>

// ---------------- problem constants ----------------
#define NB 2
#define CC 256
#define HH 100
#define WW 100
#define NROI 512
#define PP 7
#define SS 4
#define SCALEF 0.0625f
#define TRANS_STDF 0.1f
#define K1 (CC*PP*PP)     // 12544
#define DFC 1024
#define M3 (PP*PP*3)      // 147
#define NBIN (NROI*PP*PP) // 25088
#define META_W 44

// ---------------- scratch (device globals; no allocs allowed) ----------------
__device__ float g_featT[NB*HH*WW*CC];   // NHWC features
__device__ float g_X[NROI*K1];           // pooled (no-trans) features (tf32-rounded)
__device__ float g_H1[NROI*DFC];
__device__ float g_H2[NROI*DFC];
__device__ float g_OM[NROI*M3];          // offsets (2*49) + mask logit (49)
__device__ float g_part[9*NROI*DFC];     // split-K partials (18.9 MB)
__device__ float g_meta[NBIN*META_W];    // per-bin pooling metadata

// ======================= small PTX helpers (sm_80+ baseline only) =======================
__device__ __forceinline__ uint32_t smem_u32(const void* p) {
    uint32_t a;
    asm("{ .reg .u64 t; cvta.to.shared.u64 t, %1; cvt.u32.u64 %0, t; }"
        : "=r"(a) : "l"(p));
    return a;
}

__device__ __forceinline__ void cpasync16(uint32_t dst, const void* src, bool pred) {
    int sz = pred ? 16 : 0;
    asm volatile("cp.async.cg.shared.global [%0], [%1], 16, %2;"
                 :: "r"(dst), "l"(src), "r"(sz) : "memory");
}

__device__ __forceinline__ uint32_t f2tf32(float f) {
    uint32_t u;
    asm("cvt.rna.tf32.f32 %0, %1;" : "=r"(u) : "f"(f));
    return u;
}

__device__ __forceinline__ float roundtf32(float f) {
    return __uint_as_float(f2tf32(f));
}

__device__ __forceinline__ void mma_tf32(float c[4], const uint32_t a[4], const uint32_t b[2]) {
    asm volatile(
        "mma.sync.aligned.m16n8k8.row.col.f32.tf32.tf32.f32 "
        "{%0,%1,%2,%3}, {%4,%5,%6,%7}, {%8,%9}, {%0,%1,%2,%3};"
        : "+f"(c[0]), "+f"(c[1]), "+f"(c[2]), "+f"(c[3])
        : "r"(a[0]), "r"(a[1]), "r"(a[2]), "r"(a[3]), "r"(b[0]), "r"(b[1]));
}

// ---------------- NCHW -> NHWC transpose ----------------
__global__ void transpose_kernel(const float* __restrict__ feat) {
    __shared__ float tile[32][33];
    int b   = blockIdx.z;
    int hw0 = blockIdx.x * 32;
    int c0  = blockIdx.y * 32;
    int tx = threadIdx.x, ty = threadIdx.y; // (32, 8)
    const float* src = feat + (size_t)b * CC * HH * WW;
    float* dst = g_featT + (size_t)b * HH * WW * CC;
    #pragma unroll
    for (int j = 0; j < 32; j += 8) {
        int c  = c0 + ty + j;
        int hw = hw0 + tx;
        tile[ty + j][tx] = (hw < HH*WW) ? src[c * (HH*WW) + hw] : 0.0f;
    }
    __syncthreads();
    #pragma unroll
    for (int j = 0; j < 32; j += 8) {
        int hw = hw0 + ty + j;
        int c  = c0 + tx;
        if (hw < HH*WW) dst[hw * CC + c] = tile[tx][ty + j];
    }
}

// ---------------- pool metadata: one thread per bin ----------------
template<bool TRANS>
__global__ void __launch_bounds__(256) pool_meta_kernel(const float* __restrict__ rois) {
    __shared__ float swg[256 * 36];
    int tid = threadIdx.x;
    int bin = blockIdx.x * 256 + tid;
    if (bin >= NBIN) return;
    float* wg = swg + tid * 36;
    #pragma unroll
    for (int i = 0; i < 36; i++) wg[i] = 0.0f;

    int n  = bin / 49;
    int pp = bin % 49;
    int ph = pp / 7, pw = pp % 7;
    const float* r = rois + n * 5;
    int b = (int)r[0];
    float rsw = rintf(r[1]) * SCALEF - 0.5f;
    float rsh = rintf(r[2]) * SCALEF - 0.5f;
    float rew = (rintf(r[3]) + 1.0f) * SCALEF - 0.5f;
    float reh = (rintf(r[4]) + 1.0f) * SCALEF - 0.5f;
    float roi_w = fmaxf(rew - rsw, 0.1f);
    float roi_h = fmaxf(reh - rsh, 0.1f);
    float bin_h = roi_h / (float)PP;
    float bin_w = roi_w / (float)PP;
    float sub_h = bin_h / (float)SS;
    float sub_w = bin_w / (float)SS;

    float tx_ = 0.0f, ty_ = 0.0f, mask = 1.0f;
    if (TRANS) {
        int part_h = (int)floorf((float)ph / (float)PP * 7.0f);
        int part_w = (int)floorf((float)pw / (float)PP * 7.0f);
        const float* o = g_OM + n * M3;
        tx_ = o[0*49 + part_h*7 + part_w] * TRANS_STDF;
        ty_ = o[1*49 + part_h*7 + part_w] * TRANS_STDF;
        float ml = o[2*49 + pp];
        mask = 1.0f / (1.0f + expf(-ml));
    }
    float hstart = (float)ph * bin_h + rsh + ty_ * roi_h;
    float wstart = (float)pw * bin_w + rsw + tx_ * roi_w;

    int horg = (int)floorf(fminf(fmaxf(hstart, 0.0f), (float)(HH-1)));
    int worg = (int)floorf(fminf(fmaxf(wstart, 0.0f), (float)(WW-1)));
    int cnt = 0;
    #pragma unroll
    for (int iy = 0; iy < SS; iy++) {
        float h = hstart + (float)iy * sub_h;
        #pragma unroll
        for (int ix = 0; ix < SS; ix++) {
            float w = wstart + (float)ix * sub_w;
            bool valid = (w >= -0.5f) && (w <= (float)WW - 0.5f) &&
                         (h >= -0.5f) && (h <= (float)HH - 0.5f);
            if (!valid) continue;
            cnt++;
            float hc = fminf(fmaxf(h, 0.0f), (float)(HH-1));
            float wc = fminf(fmaxf(w, 0.0f), (float)(WW-1));
            int h0 = (int)floorf(hc), w0 = (int)floorf(wc);
            int h1 = min(h0 + 1, HH - 1), w1 = min(w0 + 1, WW - 1);
            float lh = hc - (float)h0, lw = wc - (float)w0;
            int r0 = min(max(h0 - horg, 0), 5);
            int r1 = min(max(h1 - horg, 0), 5);
            int c0 = min(max(w0 - worg, 0), 5);
            int c1 = min(max(w1 - worg, 0), 5);
            wg[r0*6 + c0] += (1.0f - lh) * (1.0f - lw);
            wg[r0*6 + c1] += (1.0f - lh) * lw;
            wg[r1*6 + c0] += lh * (1.0f - lw);
            wg[r1*6 + c1] += lh * lw;
        }
    }
    float* m = g_meta + (size_t)bin * META_W;
    #pragma unroll
    for (int i = 0; i < 36; i++) m[i] = wg[i];
    m[36] = (float)cnt;
    m[37] = mask;
    m[38] = __int_as_float(horg);
    m[39] = __int_as_float(worg);
    m[40] = __int_as_float(b * HH * WW * CC);
}

// ---------------- pool gather: one block per ROI (49 bins), coalesced output ----------------
// smem: 49*256 staged values + 49*41 metadata = 58.2 KB dynamic.
#define GATHER_SMEM ((49*256 + 49*41) * 4)

template<bool TRANS>
__global__ void __launch_bounds__(256) pool_gather_kernel(float* __restrict__ outp) {
    extern __shared__ float sg[];
    float* vals = sg;              // [256 c][49 pp], index c*49+pp
    float* meta = sg + 49 * 256;   // [49 pp][41]

    int n   = blockIdx.x;
    int tid = threadIdx.x;
    for (int i = tid; i < 49 * 41; i += 256) {
        int bb = i / 41, k = i - bb * 41;
        meta[i] = g_meta[(size_t)(n * 49 + bb) * META_W + k];
    }
    __syncthreads();

    int c = tid;
    #pragma unroll 1
    for (int pp = 0; pp < 49; pp++) {
        const float* m = meta + pp * 41;
        int horg = __float_as_int(m[38]);
        int worg = __float_as_int(m[39]);
        int base = __float_as_int(m[40]);
        float acc = 0.0f;
        #pragma unroll
        for (int cell = 0; cell < 36; cell++) {
            float wt = m[cell];
            if (wt != 0.0f) {
                int y = min(horg + cell / 6, HH - 1);
                int x = min(worg + cell % 6, WW - 1);
                acc += wt * g_featT[base + (y * WW + x) * CC + c];
            }
        }
        float cnt = m[36];
        float v = (cnt > 0.0f) ? (acc / cnt) : 0.0f;
        if (TRANS) v *= m[37];
        else       v = roundtf32(v);     // pre-round for GEMM A
        vals[c * 49 + pp] = v;
    }
    __syncthreads();

    float* dst = (TRANS ? outp : g_X) + (size_t)n * K1;
    #pragma unroll
    for (int i = 0; i < K1 / 256; i++)
        dst[i * 256 + tid] = vals[i * 256 + tid];
}

// ============ TF32 mma.sync GEMM with split-K, 128x128 tile, 8 warps, 2 CTA/SM ============
#define BM 128
#define BN 128
#define BK 32
#define GPAD 36
#define GSTAGES 3
#define ASZ (BM*GPAD)
#define BSZ (BN*GPAD)
#define STGSZ (ASZ+BSZ)
#define GEMM_SMEM_BYTES (GSTAGES*STGSZ*4)

template<int KDIM, int JROWS, int JS, int SPLITK>
__global__ void __launch_bounds__(256, 2) fcmma_kernel(
    const float* __restrict__ A, const float* __restrict__ Wt,
    float* __restrict__ Part)
{
    static_assert(KDIM % BK == 0, "K multiple of BK");
    constexpr int KT = KDIM / BK;
    constexpr int CH = (KT + SPLITK - 1) / SPLITK;

    extern __shared__ float sm[];
    int tid  = threadIdx.x;
    int lane = tid & 31, wid = tid >> 5;
    int m0 = blockIdx.y * BM, n0 = blockIdx.x * BN;
    int z  = blockIdx.z;
    int t0 = z * CH;
    int ntc = min(KT - t0, CH);

    int g = lane >> 2, tg = lane & 3;
    int wm = (wid & 1) * 64;        // 2 warps along M
    int wn = (wid >> 1) * 32;       // 4 warps along N

    float c[4][4][4];
    #pragma unroll
    for (int mt = 0; mt < 4; mt++)
        #pragma unroll
        for (int nt = 0; nt < 4; nt++)
            #pragma unroll
            for (int q = 0; q < 4; q++) c[mt][nt][q] = 0.0f;

    int lrow = tid >> 3;     // 0..31
    int lchk = tid & 7;      // 0..7

    auto load_stage = [&](int s, int t) {
        float* As = sm + s * STGSZ;
        float* Bs = As + ASZ;
        int kg = t * BK + lchk * 4;
        #pragma unroll
        for (int it = 0; it < 4; it++) {
            int r = lrow + it * 32;
            cpasync16(smem_u32(As + r * GPAD + lchk * 4),
                      A + (size_t)(m0 + r) * KDIM + kg, true);
            int br = n0 + r;
            bool ok = ((JROWS % BN) == 0) || (br < JROWS);
            cpasync16(smem_u32(Bs + r * GPAD + lchk * 4),
                      Wt + (size_t)(ok ? br : 0) * KDIM + kg, ok);
        }
    };

    #pragma unroll
    for (int s = 0; s < GSTAGES - 1; s++) {
        if (s < ntc) load_stage(s, t0 + s);
        asm volatile("cp.async.commit_group;" ::: "memory");
    }

    #pragma unroll 1
    for (int i = 0; i < ntc; i++) {
        asm volatile("cp.async.wait_group %0;" :: "n"(GSTAGES - 2) : "memory");
        __syncthreads();

        int tn = i + GSTAGES - 1;
        if (tn < ntc) load_stage(tn % GSTAGES, t0 + tn);
        asm volatile("cp.async.commit_group;" ::: "memory");

        const float* As = sm + (i % GSTAGES) * STGSZ;
        const float* Bs = As + ASZ;
        #pragma unroll
        for (int ks = 0; ks < 4; ks++) {
            int kk = ks * 8;
            uint32_t a[4][4], b[4][2];
            #pragma unroll
            for (int mt = 0; mt < 4; mt++) {
                int m = wm + mt * 16 + g;
                a[mt][0] = __float_as_uint(As[m * GPAD + kk + tg]);
                a[mt][1] = __float_as_uint(As[(m + 8) * GPAD + kk + tg]);
                a[mt][2] = __float_as_uint(As[m * GPAD + kk + tg + 4]);
                a[mt][3] = __float_as_uint(As[(m + 8) * GPAD + kk + tg + 4]);
            }
            #pragma unroll
            for (int nt = 0; nt < 4; nt++) {
                int nn = wn + nt * 8 + g;
                b[nt][0] = f2tf32(Bs[nn * GPAD + kk + tg]);
                b[nt][1] = f2tf32(Bs[nn * GPAD + kk + tg + 4]);
            }
            #pragma unroll
            for (int mt = 0; mt < 4; mt++)
                #pragma unroll
                for (int nt = 0; nt < 4; nt++)
                    mma_tf32(c[mt][nt], a[mt], b[nt]);
        }
        __syncthreads();
    }

    // write partials
    float* P = Part + (size_t)z * NROI * JS;
    #pragma unroll
    for (int mt = 0; mt < 4; mt++) {
        int row0 = m0 + wm + mt * 16 + g;
        #pragma unroll
        for (int nt = 0; nt < 4; nt++) {
            int j0 = n0 + wn + nt * 8 + tg * 2;
            #pragma unroll
            for (int h = 0; h < 2; h++) {
                int row = row0 + h * 8;
                float2 v = make_float2(c[mt][nt][h*2], c[mt][nt][h*2+1]);
                *reinterpret_cast<float2*>(P + (size_t)row * JS + j0) = v;
            }
        }
    }
}

// vectorized reduce: partials + bias + relu (+ tf32 round for next GEMM)
template<int J, int JS, int SPLITK, bool RELU, bool ROUND>
__global__ void __launch_bounds__(256) reduce_vec_kernel(
    const float* __restrict__ Part, const float* __restrict__ bias,
    float* __restrict__ Cout)
{
    int idx = blockIdx.x * 256 + threadIdx.x;
    if (idx >= NROI * (J / 4)) return;
    int row = idx / (J / 4), jv = idx - row * (J / 4);
    int j = jv * 4;
    float4 v = make_float4(0.f, 0.f, 0.f, 0.f);
    #pragma unroll
    for (int z = 0; z < SPLITK; z++) {
        float4 p = *reinterpret_cast<const float4*>(Part + ((size_t)z * NROI + row) * JS + j);
        v.x += p.x; v.y += p.y; v.z += p.z; v.w += p.w;
    }
    float4 bb = *reinterpret_cast<const float4*>(bias + j);
    v.x += bb.x; v.y += bb.y; v.z += bb.z; v.w += bb.w;
    if (RELU) {
        v.x = fmaxf(v.x, 0.f); v.y = fmaxf(v.y, 0.f);
        v.z = fmaxf(v.z, 0.f); v.w = fmaxf(v.w, 0.f);
    }
    if (ROUND) {
        v.x = roundtf32(v.x); v.y = roundtf32(v.y);
        v.z = roundtf32(v.z); v.w = roundtf32(v.w);
    }
    *reinterpret_cast<float4*>(Cout + (size_t)row * J + j) = v;
}

template<int J, int JS, int SPLITK, bool RELU>
__global__ void __launch_bounds__(256) reduce_kernel(
    const float* __restrict__ Part, const float* __restrict__ bias,
    float* __restrict__ Cout)
{
    int idx = blockIdx.x * 256 + threadIdx.x;
    if (idx >= NROI * J) return;
    int row = idx / J, j = idx - row * J;
    float v = 0.0f;
    #pragma unroll
    for (int z = 0; z < SPLITK; z++)
        v += Part[((size_t)z * NROI + row) * JS + j];
    v += __ldg(bias + j);
    if (RELU) v = fmaxf(v, 0.0f);
    Cout[idx] = v;
}

// ======================= launch =======================
extern "C" void kernel_launch(void* const* d_in, const int* in_sizes, int n_in,
                              void* d_out, int out_size) {
    const float* feat = (const float*)d_in[0];
    const float* rois = (const float*)d_in[1];
    const float* w1   = (const float*)d_in[2];
    const float* b1   = (const float*)d_in[3];
    const float* w2   = (const float*)d_in[4];
    const float* b2   = (const float*)d_in[5];
    const float* w3   = (const float*)d_in[6];
    const float* b3   = (const float*)d_in[7];
    float* out = (float*)d_out;

    static float *pX=nullptr, *pH1=nullptr, *pH2=nullptr, *pOM=nullptr, *pPart=nullptr;
    if (!pX) {
        void* p;
        cudaGetSymbolAddress(&p, g_X);    pX    = (float*)p;
        cudaGetSymbolAddress(&p, g_H1);   pH1   = (float*)p;
        cudaGetSymbolAddress(&p, g_H2);   pH2   = (float*)p;
        cudaGetSymbolAddress(&p, g_OM);   pOM   = (float*)p;
        cudaGetSymbolAddress(&p, g_part); pPart = (float*)p;
        cudaFuncSetAttribute(fcmma_kernel<K1,  DFC, DFC, 9>,
                             cudaFuncAttributeMaxDynamicSharedMemorySize, GEMM_SMEM_BYTES);
        cudaFuncSetAttribute(fcmma_kernel<DFC, DFC, DFC, 8>,
                             cudaFuncAttributeMaxDynamicSharedMemorySize, GEMM_SMEM_BYTES);
        cudaFuncSetAttribute(fcmma_kernel<DFC, M3,  256, 16>,
                             cudaFuncAttributeMaxDynamicSharedMemorySize, GEMM_SMEM_BYTES);
        cudaFuncSetAttribute(pool_gather_kernel<false>,
                             cudaFuncAttributeMaxDynamicSharedMemorySize, GATHER_SMEM);
        cudaFuncSetAttribute(pool_gather_kernel<true>,
                             cudaFuncAttributeMaxDynamicSharedMemorySize, GATHER_SMEM);
    }

    // 1. NCHW -> NHWC
    dim3 tb(32, 8);
    dim3 tg((HH*WW + 31) / 32, CC / 32, NB);
    transpose_kernel<<<tg, tb>>>(feat);

    // 2. pool (no offsets) -> g_X (tf32-rounded, coalesced writes)
    pool_meta_kernel<false><<<(NBIN + 255) / 256, 256>>>(rois);
    pool_gather_kernel<false><<<NROI, 256, GATHER_SMEM>>>(nullptr);

    // 3. FC stack: split-K TF32 mma.sync (128x128, 8 warps, 2 CTA/SM) + fused reduce
    fcmma_kernel<K1,  DFC, DFC, 9><<<dim3(DFC/BN, NROI/BM, 9), 256, GEMM_SMEM_BYTES>>>(pX,  w1, pPart);
    reduce_vec_kernel<DFC, DFC, 9, true, true><<<(NROI*DFC/4 + 255)/256, 256>>>(pPart, b1, pH1);

    fcmma_kernel<DFC, DFC, DFC, 8><<<dim3(DFC/BN, NROI/BM, 8), 256, GEMM_SMEM_BYTES>>>(pH1, w2, pPart);
    reduce_vec_kernel<DFC, DFC, 8, true, true><<<(NROI*DFC/4 + 255)/256, 256>>>(pPart, b2, pH2);

    fcmma_kernel<DFC, M3, 256, 16><<<dim3(2, NROI/BM, 16), 256, GEMM_SMEM_BYTES>>>(pH2, w3, pPart);
    reduce_kernel<M3, 256, 16, false><<<(NROI*M3 + 255)/256, 256>>>(pPart, b3, pOM);

    // 4. deformable pool with offsets, times sigmoid mask -> out (coalesced writes)
    pool_meta_kernel<true><<<(NBIN + 255) / 256, 256>>>(rois);
    pool_gather_kernel<true><<<NROI, 256, GATHER_SMEM>>>(out);
}

// round 8
// speedup vs baseline: 1.8207x; 1.8207x over previous
#include <cuda_runtime.h>
#include <math.h>
#include <stdint.h>

// ---------------- problem constants ----------------
#define NB 2
#define CC 256
#define HH 100
#define WW 100
#define NROI 512
#define PP 7
#define SS 4
#define SCALEF 0.0625f
#define TRANS_STDF 0.1f
#define K1 (CC*PP*PP)     // 12544
#define DFC 1024
#define M3 (PP*PP*3)      // 147
#define NBIN (NROI*PP*PP) // 25088
#define META_W 44

// ---------------- scratch (device globals; no allocs allowed) ----------------
__device__ float g_featT[NB*HH*WW*CC];   // NHWC features
__device__ float g_X[NROI*K1];           // pooled (no-trans) features (tf32-rounded)
__device__ float g_H1[NROI*DFC];
__device__ float g_H2[NROI*DFC];
__device__ float g_OM[NROI*M3];          // offsets (2*49) + mask logit (49)
__device__ float g_part[9*NROI*DFC];     // split-K partials (18.9 MB)
__device__ float g_meta[NBIN*META_W];    // per-bin pooling metadata
__device__ float g_stage[NBIN*CC];       // bin-major pooled staging (25.7 MB)

// ======================= small PTX helpers (sm_80+ baseline only) =======================
__device__ __forceinline__ uint32_t smem_u32(const void* p) {
    uint32_t a;
    asm("{ .reg .u64 t; cvta.to.shared.u64 t, %1; cvt.u32.u64 %0, t; }"
        : "=r"(a) : "l"(p));
    return a;
}

__device__ __forceinline__ void cpasync16(uint32_t dst, const void* src, bool pred) {
    int sz = pred ? 16 : 0;
    asm volatile("cp.async.cg.shared.global [%0], [%1], 16, %2;"
                 :: "r"(dst), "l"(src), "r"(sz) : "memory");
}

__device__ __forceinline__ uint32_t f2tf32(float f) {
    uint32_t u;
    asm("cvt.rna.tf32.f32 %0, %1;" : "=r"(u) : "f"(f));
    return u;
}

__device__ __forceinline__ float roundtf32(float f) {
    return __uint_as_float(f2tf32(f));
}

__device__ __forceinline__ void mma_tf32(float c[4], const uint32_t a[4], const uint32_t b[2]) {
    asm volatile(
        "mma.sync.aligned.m16n8k8.row.col.f32.tf32.tf32.f32 "
        "{%0,%1,%2,%3}, {%4,%5,%6,%7}, {%8,%9}, {%0,%1,%2,%3};"
        : "+f"(c[0]), "+f"(c[1]), "+f"(c[2]), "+f"(c[3])
        : "r"(a[0]), "r"(a[1]), "r"(a[2]), "r"(a[3]), "r"(b[0]), "r"(b[1]));
}

// ---------------- NCHW -> NHWC transpose ----------------
__global__ void transpose_kernel(const float* __restrict__ feat) {
    __shared__ float tile[32][33];
    int b   = blockIdx.z;
    int hw0 = blockIdx.x * 32;
    int c0  = blockIdx.y * 32;
    int tx = threadIdx.x, ty = threadIdx.y; // (32, 8)
    const float* src = feat + (size_t)b * CC * HH * WW;
    float* dst = g_featT + (size_t)b * HH * WW * CC;
    #pragma unroll
    for (int j = 0; j < 32; j += 8) {
        int c  = c0 + ty + j;
        int hw = hw0 + tx;
        tile[ty + j][tx] = (hw < HH*WW) ? src[c * (HH*WW) + hw] : 0.0f;
    }
    __syncthreads();
    #pragma unroll
    for (int j = 0; j < 32; j += 8) {
        int hw = hw0 + ty + j;
        int c  = c0 + tx;
        if (hw < HH*WW) dst[hw * CC + c] = tile[tx][ty + j];
    }
}

// ---------------- pool metadata: one thread per bin ----------------
template<bool TRANS>
__global__ void __launch_bounds__(256) pool_meta_kernel(const float* __restrict__ rois) {
    __shared__ float swg[256 * 36];
    int tid = threadIdx.x;
    int bin = blockIdx.x * 256 + tid;
    if (bin >= NBIN) return;
    float* wg = swg + tid * 36;
    #pragma unroll
    for (int i = 0; i < 36; i++) wg[i] = 0.0f;

    int n  = bin / 49;
    int pp = bin % 49;
    int ph = pp / 7, pw = pp % 7;
    const float* r = rois + n * 5;
    int b = (int)r[0];
    float rsw = rintf(r[1]) * SCALEF - 0.5f;
    float rsh = rintf(r[2]) * SCALEF - 0.5f;
    float rew = (rintf(r[3]) + 1.0f) * SCALEF - 0.5f;
    float reh = (rintf(r[4]) + 1.0f) * SCALEF - 0.5f;
    float roi_w = fmaxf(rew - rsw, 0.1f);
    float roi_h = fmaxf(reh - rsh, 0.1f);
    float bin_h = roi_h / (float)PP;
    float bin_w = roi_w / (float)PP;
    float sub_h = bin_h / (float)SS;
    float sub_w = bin_w / (float)SS;

    float tx_ = 0.0f, ty_ = 0.0f, mask = 1.0f;
    if (TRANS) {
        int part_h = (int)floorf((float)ph / (float)PP * 7.0f);
        int part_w = (int)floorf((float)pw / (float)PP * 7.0f);
        const float* o = g_OM + n * M3;
        tx_ = o[0*49 + part_h*7 + part_w] * TRANS_STDF;
        ty_ = o[1*49 + part_h*7 + part_w] * TRANS_STDF;
        float ml = o[2*49 + pp];
        mask = 1.0f / (1.0f + expf(-ml));
    }
    float hstart = (float)ph * bin_h + rsh + ty_ * roi_h;
    float wstart = (float)pw * bin_w + rsw + tx_ * roi_w;

    int horg = (int)floorf(fminf(fmaxf(hstart, 0.0f), (float)(HH-1)));
    int worg = (int)floorf(fminf(fmaxf(wstart, 0.0f), (float)(WW-1)));
    int cnt = 0;
    #pragma unroll
    for (int iy = 0; iy < SS; iy++) {
        float h = hstart + (float)iy * sub_h;
        #pragma unroll
        for (int ix = 0; ix < SS; ix++) {
            float w = wstart + (float)ix * sub_w;
            bool valid = (w >= -0.5f) && (w <= (float)WW - 0.5f) &&
                         (h >= -0.5f) && (h <= (float)HH - 0.5f);
            if (!valid) continue;
            cnt++;
            float hc = fminf(fmaxf(h, 0.0f), (float)(HH-1));
            float wc = fminf(fmaxf(w, 0.0f), (float)(WW-1));
            int h0 = (int)floorf(hc), w0 = (int)floorf(wc);
            int h1 = min(h0 + 1, HH - 1), w1 = min(w0 + 1, WW - 1);
            float lh = hc - (float)h0, lw = wc - (float)w0;
            int r0 = min(max(h0 - horg, 0), 5);
            int r1 = min(max(h1 - horg, 0), 5);
            int c0 = min(max(w0 - worg, 0), 5);
            int c1 = min(max(w1 - worg, 0), 5);
            wg[r0*6 + c0] += (1.0f - lh) * (1.0f - lw);
            wg[r0*6 + c1] += (1.0f - lh) * lw;
            wg[r1*6 + c0] += lh * (1.0f - lw);
            wg[r1*6 + c1] += lh * lw;
        }
    }
    float invc = (cnt > 0) ? (1.0f / (float)cnt) : 0.0f;
    float* m = g_meta + (size_t)bin * META_W;
    #pragma unroll
    for (int i = 0; i < 36; i++) m[i] = wg[i] * invc;   // fold 1/cnt into weights
    m[36] = (cnt > 0) ? 1.0f : 0.0f;
    m[37] = mask;
    m[38] = __int_as_float(horg);
    m[39] = __int_as_float(worg);
    m[40] = __int_as_float(b * HH * WW * CC);
}

// ---------------- pool gather: 4 bins/block, 64 threads/bin, float4 channels ----------------
// Writes bin-major staging g_stage[(n*49+pp)*256 + c] -- fully coalesced.
template<bool TRANS>
__global__ void __launch_bounds__(256) pool_gather_kernel() {
    __shared__ float meta[4][41];
    int tid = threadIdx.x;
    int sub = tid >> 6;        // bin slot 0..3
    int l64 = tid & 63;        // channel group: 4 channels each
    int bin0 = blockIdx.x * 4;

    if (tid < 4 * 41) {
        int bb = tid / 41, k = tid - bb * 41;
        meta[bb][k] = g_meta[(size_t)(bin0 + bb) * META_W + k];
    }
    __syncthreads();

    const float* m = meta[sub];
    int horg = __float_as_int(m[38]);
    int worg = __float_as_int(m[39]);
    int base = __float_as_int(m[40]);
    float mask = m[37];
    float ok   = m[36];

    float4 acc = make_float4(0.f, 0.f, 0.f, 0.f);
    #pragma unroll
    for (int cell = 0; cell < 36; cell++) {
        float wt = m[cell];
        if (wt != 0.0f) {
            int y = min(horg + cell / 6, HH - 1);
            int x = min(worg + cell % 6, WW - 1);
            float4 f = *reinterpret_cast<const float4*>(
                g_featT + base + (y * WW + x) * CC + l64 * 4);
            acc.x += wt * f.x; acc.y += wt * f.y;
            acc.z += wt * f.z; acc.w += wt * f.w;
        }
    }
    float4 v;
    if (TRANS) {
        float s = ok * mask;
        v = make_float4(acc.x * s, acc.y * s, acc.z * s, acc.w * s);
    } else {
        v = make_float4(roundtf32(acc.x * ok), roundtf32(acc.y * ok),
                        roundtf32(acc.z * ok), roundtf32(acc.w * ok));
    }
    *reinterpret_cast<float4*>(g_stage + (size_t)(bin0 + sub) * CC + l64 * 4) = v;
}

// ---------------- layout fix: (n,pp,c) staging -> (n,c,pp) output ----------------
#define FIX_SMEM (49 * 257 * 4)
__global__ void __launch_bounds__(256) layout_fix_kernel(float* __restrict__ dstbuf) {
    extern __shared__ float s[];
    int n   = blockIdx.x;
    int tid = threadIdx.x;
    const float* src = g_stage + (size_t)n * 49 * CC;
    #pragma unroll
    for (int pp = 0; pp < 49; pp++)
        s[pp * 257 + tid] = src[pp * CC + tid];
    __syncthreads();
    float* dst = dstbuf + (size_t)n * K1;
    #pragma unroll
    for (int i = 0; i < 49; i++) {
        int k = i * 256 + tid;
        int c = k / 49, pp = k - c * 49;
        dst[k] = s[pp * 257 + c];
    }
}

// ============ TF32 mma.sync GEMM with split-K, 128x128 tile, 8 warps, 2 CTA/SM ============
#define BM 128
#define BN 128
#define BK 32
#define GPAD 36
#define GSTAGES 3
#define ASZ (BM*GPAD)
#define BSZ (BN*GPAD)
#define STGSZ (ASZ+BSZ)
#define GEMM_SMEM_BYTES (GSTAGES*STGSZ*4)

template<int KDIM, int JROWS, int JS, int SPLITK>
__global__ void __launch_bounds__(256, 2) fcmma_kernel(
    const float* __restrict__ A, const float* __restrict__ Wt,
    float* __restrict__ Part)
{
    static_assert(KDIM % BK == 0, "K multiple of BK");
    constexpr int KT = KDIM / BK;
    constexpr int CH = (KT + SPLITK - 1) / SPLITK;

    extern __shared__ float sm[];
    int tid  = threadIdx.x;
    int lane = tid & 31, wid = tid >> 5;
    int m0 = blockIdx.y * BM, n0 = blockIdx.x * BN;
    int z  = blockIdx.z;
    int t0 = z * CH;
    int ntc = min(KT - t0, CH);

    int g = lane >> 2, tg = lane & 3;
    int wm = (wid & 1) * 64;
    int wn = (wid >> 1) * 32;

    float c[4][4][4];
    #pragma unroll
    for (int mt = 0; mt < 4; mt++)
        #pragma unroll
        for (int nt = 0; nt < 4; nt++)
            #pragma unroll
            for (int q = 0; q < 4; q++) c[mt][nt][q] = 0.0f;

    int lrow = tid >> 3;
    int lchk = tid & 7;

    auto load_stage = [&](int s, int t) {
        float* As = sm + s * STGSZ;
        float* Bs = As + ASZ;
        int kg = t * BK + lchk * 4;
        #pragma unroll
        for (int it = 0; it < 4; it++) {
            int r = lrow + it * 32;
            cpasync16(smem_u32(As + r * GPAD + lchk * 4),
                      A + (size_t)(m0 + r) * KDIM + kg, true);
            int br = n0 + r;
            bool ok = ((JROWS % BN) == 0) || (br < JROWS);
            cpasync16(smem_u32(Bs + r * GPAD + lchk * 4),
                      Wt + (size_t)(ok ? br : 0) * KDIM + kg, ok);
        }
    };

    #pragma unroll
    for (int s = 0; s < GSTAGES - 1; s++) {
        if (s < ntc) load_stage(s, t0 + s);
        asm volatile("cp.async.commit_group;" ::: "memory");
    }

    #pragma unroll 1
    for (int i = 0; i < ntc; i++) {
        asm volatile("cp.async.wait_group %0;" :: "n"(GSTAGES - 2) : "memory");
        __syncthreads();

        int tn = i + GSTAGES - 1;
        if (tn < ntc) load_stage(tn % GSTAGES, t0 + tn);
        asm volatile("cp.async.commit_group;" ::: "memory");

        const float* As = sm + (i % GSTAGES) * STGSZ;
        const float* Bs = As + ASZ;
        #pragma unroll
        for (int ks = 0; ks < 4; ks++) {
            int kk = ks * 8;
            uint32_t a[4][4], b[4][2];
            #pragma unroll
            for (int mt = 0; mt < 4; mt++) {
                int m = wm + mt * 16 + g;
                a[mt][0] = __float_as_uint(As[m * GPAD + kk + tg]);
                a[mt][1] = __float_as_uint(As[(m + 8) * GPAD + kk + tg]);
                a[mt][2] = __float_as_uint(As[m * GPAD + kk + tg + 4]);
                a[mt][3] = __float_as_uint(As[(m + 8) * GPAD + kk + tg + 4]);
            }
            #pragma unroll
            for (int nt = 0; nt < 4; nt++) {
                int nn = wn + nt * 8 + g;
                b[nt][0] = f2tf32(Bs[nn * GPAD + kk + tg]);
                b[nt][1] = f2tf32(Bs[nn * GPAD + kk + tg + 4]);
            }
            #pragma unroll
            for (int mt = 0; mt < 4; mt++)
                #pragma unroll
                for (int nt = 0; nt < 4; nt++)
                    mma_tf32(c[mt][nt], a[mt], b[nt]);
        }
        __syncthreads();
    }

    float* P = Part + (size_t)z * NROI * JS;
    #pragma unroll
    for (int mt = 0; mt < 4; mt++) {
        int row0 = m0 + wm + mt * 16 + g;
        #pragma unroll
        for (int nt = 0; nt < 4; nt++) {
            int j0 = n0 + wn + nt * 8 + tg * 2;
            #pragma unroll
            for (int h = 0; h < 2; h++) {
                int row = row0 + h * 8;
                float2 v = make_float2(c[mt][nt][h*2], c[mt][nt][h*2+1]);
                *reinterpret_cast<float2*>(P + (size_t)row * JS + j0) = v;
            }
        }
    }
}

// vectorized reduce: partials + bias + relu (+ tf32 round for next GEMM)
template<int J, int JS, int SPLITK, bool RELU, bool ROUND>
__global__ void __launch_bounds__(256) reduce_vec_kernel(
    const float* __restrict__ Part, const float* __restrict__ bias,
    float* __restrict__ Cout)
{
    int idx = blockIdx.x * 256 + threadIdx.x;
    if (idx >= NROI * (J / 4)) return;
    int row = idx / (J / 4), jv = idx - row * (J / 4);
    int j = jv * 4;
    float4 v = make_float4(0.f, 0.f, 0.f, 0.f);
    #pragma unroll
    for (int z = 0; z < SPLITK; z++) {
        float4 p = *reinterpret_cast<const float4*>(Part + ((size_t)z * NROI + row) * JS + j);
        v.x += p.x; v.y += p.y; v.z += p.z; v.w += p.w;
    }
    float4 bb = *reinterpret_cast<const float4*>(bias + j);
    v.x += bb.x; v.y += bb.y; v.z += bb.z; v.w += bb.w;
    if (RELU) {
        v.x = fmaxf(v.x, 0.f); v.y = fmaxf(v.y, 0.f);
        v.z = fmaxf(v.z, 0.f); v.w = fmaxf(v.w, 0.f);
    }
    if (ROUND) {
        v.x = roundtf32(v.x); v.y = roundtf32(v.y);
        v.z = roundtf32(v.z); v.w = roundtf32(v.w);
    }
    *reinterpret_cast<float4*>(Cout + (size_t)row * J + j) = v;
}

template<int J, int JS, int SPLITK, bool RELU>
__global__ void __launch_bounds__(256) reduce_kernel(
    const float* __restrict__ Part, const float* __restrict__ bias,
    float* __restrict__ Cout)
{
    int idx = blockIdx.x * 256 + threadIdx.x;
    if (idx >= NROI * J) return;
    int row = idx / J, j = idx - row * J;
    float v = 0.0f;
    #pragma unroll
    for (int z = 0; z < SPLITK; z++)
        v += Part[((size_t)z * NROI + row) * JS + j];
    v += __ldg(bias + j);
    if (RELU) v = fmaxf(v, 0.0f);
    Cout[idx] = v;
}

// ======================= launch =======================
extern "C" void kernel_launch(void* const* d_in, const int* in_sizes, int n_in,
                              void* d_out, int out_size) {
    const float* feat = (const float*)d_in[0];
    const float* rois = (const float*)d_in[1];
    const float* w1   = (const float*)d_in[2];
    const float* b1   = (const float*)d_in[3];
    const float* w2   = (const float*)d_in[4];
    const float* b2   = (const float*)d_in[5];
    const float* w3   = (const float*)d_in[6];
    const float* b3   = (const float*)d_in[7];
    float* out = (float*)d_out;

    static float *pX=nullptr, *pH1=nullptr, *pH2=nullptr, *pOM=nullptr, *pPart=nullptr;
    if (!pX) {
        void* p;
        cudaGetSymbolAddress(&p, g_X);    pX    = (float*)p;
        cudaGetSymbolAddress(&p, g_H1);   pH1   = (float*)p;
        cudaGetSymbolAddress(&p, g_H2);   pH2   = (float*)p;
        cudaGetSymbolAddress(&p, g_OM);   pOM   = (float*)p;
        cudaGetSymbolAddress(&p, g_part); pPart = (float*)p;
        cudaFuncSetAttribute(fcmma_kernel<K1,  DFC, DFC, 9>,
                             cudaFuncAttributeMaxDynamicSharedMemorySize, GEMM_SMEM_BYTES);
        cudaFuncSetAttribute(fcmma_kernel<DFC, DFC, DFC, 8>,
                             cudaFuncAttributeMaxDynamicSharedMemorySize, GEMM_SMEM_BYTES);
        cudaFuncSetAttribute(fcmma_kernel<DFC, M3,  256, 16>,
                             cudaFuncAttributeMaxDynamicSharedMemorySize, GEMM_SMEM_BYTES);
        cudaFuncSetAttribute(layout_fix_kernel,
                             cudaFuncAttributeMaxDynamicSharedMemorySize, FIX_SMEM);
    }

    // 1. NCHW -> NHWC
    dim3 tb(32, 8);
    dim3 tg((HH*WW + 31) / 32, CC / 32, NB);
    transpose_kernel<<<tg, tb>>>(feat);

    // 2. pool (no offsets) -> staging -> g_X (tf32-rounded, coalesced)
    pool_meta_kernel<false><<<(NBIN + 255) / 256, 256>>>(rois);
    pool_gather_kernel<false><<<NBIN / 4, 256>>>();
    layout_fix_kernel<<<NROI, 256, FIX_SMEM>>>(pX);

    // 3. FC stack: split-K TF32 mma.sync (128x128, 8 warps, 2 CTA/SM) + fused reduce
    fcmma_kernel<K1,  DFC, DFC, 9><<<dim3(DFC/BN, NROI/BM, 9), 256, GEMM_SMEM_BYTES>>>(pX,  w1, pPart);
    reduce_vec_kernel<DFC, DFC, 9, true, true><<<(NROI*DFC/4 + 255)/256, 256>>>(pPart, b1, pH1);

    fcmma_kernel<DFC, DFC, DFC, 8><<<dim3(DFC/BN, NROI/BM, 8), 256, GEMM_SMEM_BYTES>>>(pH1, w2, pPart);
    reduce_vec_kernel<DFC, DFC, 8, true, true><<<(NROI*DFC/4 + 255)/256, 256>>>(pPart, b2, pH2);

    fcmma_kernel<DFC, M3, 256, 16><<<dim3(2, NROI/BM, 16), 256, GEMM_SMEM_BYTES>>>(pH2, w3, pPart);
    reduce_kernel<M3, 256, 16, false><<<(NROI*M3 + 255)/256, 256>>>(pPart, b3, pOM);

    // 4. deformable pool with offsets (+mask) -> staging -> out (coalesced)
    pool_meta_kernel<true><<<(NBIN + 255) / 256, 256>>>(rois);
    pool_gather_kernel<true><<<NBIN / 4, 256>>>();
    layout_fix_kernel<<<NROI, 256, FIX_SMEM>>>(out);
}

// round 9
// speedup vs baseline: 1.8711x; 1.0277x over previous
#include <cuda_runtime.h>
#include <math.h>
#include <stdint.h>

// ---------------- problem constants ----------------
#define NB 2
#define CC 256
#define HH 100
#define WW 100
#define NROI 512
#define PP 7
#define SS 4
#define SCALEF 0.0625f
#define TRANS_STDF 0.1f
#define K1 (CC*PP*PP)     // 12544
#define DFC 1024
#define M3 (PP*PP*3)      // 147
#define NBIN (NROI*PP*PP) // 25088
#define META_W 44

// ---------------- scratch (device globals; no allocs allowed) ----------------
__device__ float g_featT[NB*HH*WW*CC];   // NHWC features
__device__ float g_X[NROI*K1];           // pooled (no-trans) features (tf32-rounded)
__device__ float g_H1[NROI*DFC];
__device__ float g_H2[NROI*DFC];
__device__ float g_OM[NROI*M3];          // offsets (2*49) + mask logit (49)
__device__ float g_part[9*NROI*DFC];     // split-K partials (18.9 MB)
__device__ float g_meta[NBIN*META_W];    // per-bin pooling metadata
__device__ float g_stage[NBIN*CC];       // bin-major pooled staging (25.7 MB)

// ======================= small PTX helpers (sm_80+ baseline only) =======================
__device__ __forceinline__ uint32_t smem_u32(const void* p) {
    uint32_t a;
    asm("{ .reg .u64 t; cvta.to.shared.u64 t, %1; cvt.u32.u64 %0, t; }"
        : "=r"(a) : "l"(p));
    return a;
}

__device__ __forceinline__ void cpasync16(uint32_t dst, const void* src, bool pred) {
    int sz = pred ? 16 : 0;
    asm volatile("cp.async.cg.shared.global [%0], [%1], 16, %2;"
                 :: "r"(dst), "l"(src), "r"(sz) : "memory");
}

__device__ __forceinline__ uint32_t f2tf32(float f) {
    uint32_t u;
    asm("cvt.rna.tf32.f32 %0, %1;" : "=r"(u) : "f"(f));
    return u;
}

__device__ __forceinline__ float roundtf32(float f) {
    return __uint_as_float(f2tf32(f));
}

__device__ __forceinline__ void mma_tf32(float c[4], const uint32_t a[4], const uint32_t b[2]) {
    asm volatile(
        "mma.sync.aligned.m16n8k8.row.col.f32.tf32.tf32.f32 "
        "{%0,%1,%2,%3}, {%4,%5,%6,%7}, {%8,%9}, {%0,%1,%2,%3};"
        : "+f"(c[0]), "+f"(c[1]), "+f"(c[2]), "+f"(c[3])
        : "r"(a[0]), "r"(a[1]), "r"(a[2]), "r"(a[3]), "r"(b[0]), "r"(b[1]));
}

// ---------------- NCHW -> NHWC transpose ----------------
__global__ void transpose_kernel(const float* __restrict__ feat) {
    __shared__ float tile[32][33];
    int b   = blockIdx.z;
    int hw0 = blockIdx.x * 32;
    int c0  = blockIdx.y * 32;
    int tx = threadIdx.x, ty = threadIdx.y; // (32, 8)
    const float* src = feat + (size_t)b * CC * HH * WW;
    float* dst = g_featT + (size_t)b * HH * WW * CC;
    #pragma unroll
    for (int j = 0; j < 32; j += 8) {
        int c  = c0 + ty + j;
        int hw = hw0 + tx;
        tile[ty + j][tx] = (hw < HH*WW) ? src[c * (HH*WW) + hw] : 0.0f;
    }
    __syncthreads();
    #pragma unroll
    for (int j = 0; j < 32; j += 8) {
        int hw = hw0 + ty + j;
        int c  = c0 + tx;
        if (hw < HH*WW) dst[hw * CC + c] = tile[tx][ty + j];
    }
}

// ---------------- pool metadata: one thread per bin ----------------
template<bool TRANS>
__global__ void __launch_bounds__(256) pool_meta_kernel(const float* __restrict__ rois) {
    __shared__ float swg[256 * 36];
    int tid = threadIdx.x;
    int bin = blockIdx.x * 256 + tid;
    if (bin >= NBIN) return;
    float* wg = swg + tid * 36;
    #pragma unroll
    for (int i = 0; i < 36; i++) wg[i] = 0.0f;

    int n  = bin / 49;
    int pp = bin % 49;
    int ph = pp / 7, pw = pp % 7;
    const float* r = rois + n * 5;
    int b = (int)r[0];
    float rsw = rintf(r[1]) * SCALEF - 0.5f;
    float rsh = rintf(r[2]) * SCALEF - 0.5f;
    float rew = (rintf(r[3]) + 1.0f) * SCALEF - 0.5f;
    float reh = (rintf(r[4]) + 1.0f) * SCALEF - 0.5f;
    float roi_w = fmaxf(rew - rsw, 0.1f);
    float roi_h = fmaxf(reh - rsh, 0.1f);
    float bin_h = roi_h / (float)PP;
    float bin_w = roi_w / (float)PP;
    float sub_h = bin_h / (float)SS;
    float sub_w = bin_w / (float)SS;

    float tx_ = 0.0f, ty_ = 0.0f, mask = 1.0f;
    if (TRANS) {
        int part_h = (int)floorf((float)ph / (float)PP * 7.0f);
        int part_w = (int)floorf((float)pw / (float)PP * 7.0f);
        const float* o = g_OM + n * M3;
        tx_ = o[0*49 + part_h*7 + part_w] * TRANS_STDF;
        ty_ = o[1*49 + part_h*7 + part_w] * TRANS_STDF;
        float ml = o[2*49 + pp];
        mask = 1.0f / (1.0f + expf(-ml));
    }
    float hstart = (float)ph * bin_h + rsh + ty_ * roi_h;
    float wstart = (float)pw * bin_w + rsw + tx_ * roi_w;

    int horg = (int)floorf(fminf(fmaxf(hstart, 0.0f), (float)(HH-1)));
    int worg = (int)floorf(fminf(fmaxf(wstart, 0.0f), (float)(WW-1)));
    int cnt = 0;
    #pragma unroll
    for (int iy = 0; iy < SS; iy++) {
        float h = hstart + (float)iy * sub_h;
        #pragma unroll
        for (int ix = 0; ix < SS; ix++) {
            float w = wstart + (float)ix * sub_w;
            bool valid = (w >= -0.5f) && (w <= (float)WW - 0.5f) &&
                         (h >= -0.5f) && (h <= (float)HH - 0.5f);
            if (!valid) continue;
            cnt++;
            float hc = fminf(fmaxf(h, 0.0f), (float)(HH-1));
            float wc = fminf(fmaxf(w, 0.0f), (float)(WW-1));
            int h0 = (int)floorf(hc), w0 = (int)floorf(wc);
            int h1 = min(h0 + 1, HH - 1), w1 = min(w0 + 1, WW - 1);
            float lh = hc - (float)h0, lw = wc - (float)w0;
            int r0 = min(max(h0 - horg, 0), 5);
            int r1 = min(max(h1 - horg, 0), 5);
            int c0 = min(max(w0 - worg, 0), 5);
            int c1 = min(max(w1 - worg, 0), 5);
            wg[r0*6 + c0] += (1.0f - lh) * (1.0f - lw);
            wg[r0*6 + c1] += (1.0f - lh) * lw;
            wg[r1*6 + c0] += lh * (1.0f - lw);
            wg[r1*6 + c1] += lh * lw;
        }
    }
    float invc = (cnt > 0) ? (1.0f / (float)cnt) : 0.0f;
    float* m = g_meta + (size_t)bin * META_W;
    #pragma unroll
    for (int i = 0; i < 36; i++) m[i] = wg[i] * invc;   // fold 1/cnt into weights
    m[36] = (cnt > 0) ? 1.0f : 0.0f;
    m[37] = mask;
    m[38] = __int_as_float(horg);
    m[39] = __int_as_float(worg);
    m[40] = __int_as_float(b * HH * WW * CC);
}

// ---------------- pool gather: 4 bins/block, 64 threads/bin, float4 channels ----------------
template<bool TRANS>
__global__ void __launch_bounds__(256) pool_gather_kernel() {
    __shared__ float meta[4][41];
    int tid = threadIdx.x;
    int sub = tid >> 6;
    int l64 = tid & 63;
    int bin0 = blockIdx.x * 4;

    if (tid < 4 * 41) {
        int bb = tid / 41, k = tid - bb * 41;
        meta[bb][k] = g_meta[(size_t)(bin0 + bb) * META_W + k];
    }
    __syncthreads();

    const float* m = meta[sub];
    int horg = __float_as_int(m[38]);
    int worg = __float_as_int(m[39]);
    int base = __float_as_int(m[40]);
    float mask = m[37];
    float ok   = m[36];

    float4 acc = make_float4(0.f, 0.f, 0.f, 0.f);
    #pragma unroll
    for (int cell = 0; cell < 36; cell++) {
        float wt = m[cell];
        if (wt != 0.0f) {
            int y = min(horg + cell / 6, HH - 1);
            int x = min(worg + cell % 6, WW - 1);
            float4 f = *reinterpret_cast<const float4*>(
                g_featT + base + (y * WW + x) * CC + l64 * 4);
            acc.x += wt * f.x; acc.y += wt * f.y;
            acc.z += wt * f.z; acc.w += wt * f.w;
        }
    }
    float4 v;
    if (TRANS) {
        float s = ok * mask;
        v = make_float4(acc.x * s, acc.y * s, acc.z * s, acc.w * s);
    } else {
        v = make_float4(roundtf32(acc.x * ok), roundtf32(acc.y * ok),
                        roundtf32(acc.z * ok), roundtf32(acc.w * ok));
    }
    *reinterpret_cast<float4*>(g_stage + (size_t)(bin0 + sub) * CC + l64 * 4) = v;
}

// ---------------- layout fix: (n,pp,c) staging -> (n,c,pp) output ----------------
#define FIX_SMEM (49 * 257 * 4)
__global__ void __launch_bounds__(256) layout_fix_kernel(float* __restrict__ dstbuf) {
    extern __shared__ float s[];
    int n   = blockIdx.x;
    int tid = threadIdx.x;
    const float* src = g_stage + (size_t)n * 49 * CC;
    #pragma unroll
    for (int pp = 0; pp < 49; pp++)
        s[pp * 257 + tid] = src[pp * CC + tid];
    __syncthreads();
    float* dst = dstbuf + (size_t)n * K1;
    #pragma unroll
    for (int i = 0; i < 49; i++) {
        int k = i * 256 + tid;
        int c = k / 49, pp = k - c * 49;
        dst[k] = s[pp * 257 + c];
    }
}

// ============ TF32 mma.sync GEMM, split-K, BM=128 x BN=256, 8 warps x 64x64 ============
#define BM 128
#define BN 256
#define BK 32
#define GPAD 36
#define GSTAGES 4
#define ASZ (BM*GPAD)
#define BSZ (BN*GPAD)
#define STGSZ (ASZ+BSZ)
#define GEMM_SMEM_BYTES (GSTAGES*STGSZ*4)   // 221184 B

template<int KDIM, int JROWS, int JS, int SPLITK>
__global__ void __launch_bounds__(256) fcmma_kernel(
    const float* __restrict__ A, const float* __restrict__ Wt,
    float* __restrict__ Part)
{
    static_assert(KDIM % BK == 0, "K multiple of BK");
    constexpr int KT = KDIM / BK;
    constexpr int CH = (KT + SPLITK - 1) / SPLITK;

    extern __shared__ float sm[];
    int tid  = threadIdx.x;
    int lane = tid & 31, wid = tid >> 5;
    int m0 = blockIdx.y * BM, n0 = blockIdx.x * BN;
    int z  = blockIdx.z;
    int t0 = z * CH;
    int ntc = min(KT - t0, CH);

    int g = lane >> 2, tg = lane & 3;
    int wm = (wid & 1) * 64;        // 2 warps along M (64 rows each)
    int wn = (wid >> 1) * 64;       // 4 warps along N (64 cols each)

    float c[4][8][4];
    #pragma unroll
    for (int mt = 0; mt < 4; mt++)
        #pragma unroll
        for (int nt = 0; nt < 8; nt++)
            #pragma unroll
            for (int q = 0; q < 4; q++) c[mt][nt][q] = 0.0f;

    int lrow = tid >> 3;     // 0..31
    int lchk = tid & 7;      // 0..7

    auto load_stage = [&](int s, int t) {
        float* As = sm + s * STGSZ;
        float* Bs = As + ASZ;
        int kg = t * BK + lchk * 4;
        #pragma unroll
        for (int it = 0; it < 4; it++) {
            int r = lrow + it * 32;
            cpasync16(smem_u32(As + r * GPAD + lchk * 4),
                      A + (size_t)(m0 + r) * KDIM + kg, true);
        }
        #pragma unroll
        for (int it = 0; it < 8; it++) {
            int r = lrow + it * 32;
            int br = n0 + r;
            bool ok = ((JROWS % BN) == 0) || (br < JROWS);
            cpasync16(smem_u32(Bs + r * GPAD + lchk * 4),
                      Wt + (size_t)(ok ? br : 0) * KDIM + kg, ok);
        }
    };

    #pragma unroll
    for (int s = 0; s < GSTAGES - 1; s++) {
        if (s < ntc) load_stage(s, t0 + s);
        asm volatile("cp.async.commit_group;" ::: "memory");
    }

    #pragma unroll 1
    for (int i = 0; i < ntc; i++) {
        asm volatile("cp.async.wait_group %0;" :: "n"(GSTAGES - 2) : "memory");
        __syncthreads();

        int tn = i + GSTAGES - 1;
        if (tn < ntc) load_stage(tn % GSTAGES, t0 + tn);
        asm volatile("cp.async.commit_group;" ::: "memory");

        const float* As = sm + (i % GSTAGES) * STGSZ;
        const float* Bs = As + ASZ;
        #pragma unroll
        for (int ks = 0; ks < 4; ks++) {
            int kk = ks * 8;
            uint32_t a[4][4], b[8][2];
            #pragma unroll
            for (int mt = 0; mt < 4; mt++) {
                int m = wm + mt * 16 + g;
                a[mt][0] = __float_as_uint(As[m * GPAD + kk + tg]);
                a[mt][1] = __float_as_uint(As[(m + 8) * GPAD + kk + tg]);
                a[mt][2] = __float_as_uint(As[m * GPAD + kk + tg + 4]);
                a[mt][3] = __float_as_uint(As[(m + 8) * GPAD + kk + tg + 4]);
            }
            #pragma unroll
            for (int nt = 0; nt < 8; nt++) {
                int nn = wn + nt * 8 + g;
                b[nt][0] = f2tf32(Bs[nn * GPAD + kk + tg]);
                b[nt][1] = f2tf32(Bs[nn * GPAD + kk + tg + 4]);
            }
            #pragma unroll
            for (int mt = 0; mt < 4; mt++)
                #pragma unroll
                for (int nt = 0; nt < 8; nt++)
                    mma_tf32(c[mt][nt], a[mt], b[nt]);
        }
        __syncthreads();
    }

    float* P = Part + (size_t)z * NROI * JS;
    #pragma unroll
    for (int mt = 0; mt < 4; mt++) {
        int row0 = m0 + wm + mt * 16 + g;
        #pragma unroll
        for (int nt = 0; nt < 8; nt++) {
            int j0 = n0 + wn + nt * 8 + tg * 2;
            #pragma unroll
            for (int h = 0; h < 2; h++) {
                int row = row0 + h * 8;
                float2 v = make_float2(c[mt][nt][h*2], c[mt][nt][h*2+1]);
                *reinterpret_cast<float2*>(P + (size_t)row * JS + j0) = v;
            }
        }
    }
}

// vectorized reduce: partials + bias + relu (+ tf32 round for next GEMM)
template<int J, int JS, int SPLITK, bool RELU, bool ROUND>
__global__ void __launch_bounds__(256) reduce_vec_kernel(
    const float* __restrict__ Part, const float* __restrict__ bias,
    float* __restrict__ Cout)
{
    int idx = blockIdx.x * 256 + threadIdx.x;
    if (idx >= NROI * (J / 4)) return;
    int row = idx / (J / 4), jv = idx - row * (J / 4);
    int j = jv * 4;
    float4 v = make_float4(0.f, 0.f, 0.f, 0.f);
    #pragma unroll
    for (int z = 0; z < SPLITK; z++) {
        float4 p = *reinterpret_cast<const float4*>(Part + ((size_t)z * NROI + row) * JS + j);
        v.x += p.x; v.y += p.y; v.z += p.z; v.w += p.w;
    }
    float4 bb = *reinterpret_cast<const float4*>(bias + j);
    v.x += bb.x; v.y += bb.y; v.z += bb.z; v.w += bb.w;
    if (RELU) {
        v.x = fmaxf(v.x, 0.f); v.y = fmaxf(v.y, 0.f);
        v.z = fmaxf(v.z, 0.f); v.w = fmaxf(v.w, 0.f);
    }
    if (ROUND) {
        v.x = roundtf32(v.x); v.y = roundtf32(v.y);
        v.z = roundtf32(v.z); v.w = roundtf32(v.w);
    }
    *reinterpret_cast<float4*>(Cout + (size_t)row * J + j) = v;
}

template<int J, int JS, int SPLITK, bool RELU>
__global__ void __launch_bounds__(256) reduce_kernel(
    const float* __restrict__ Part, const float* __restrict__ bias,
    float* __restrict__ Cout)
{
    int idx = blockIdx.x * 256 + threadIdx.x;
    if (idx >= NROI * J) return;
    int row = idx / J, j = idx - row * J;
    float v = 0.0f;
    #pragma unroll
    for (int z = 0; z < SPLITK; z++)
        v += Part[((size_t)z * NROI + row) * JS + j];
    v += __ldg(bias + j);
    if (RELU) v = fmaxf(v, 0.0f);
    Cout[idx] = v;
}

// ======================= launch =======================
extern "C" void kernel_launch(void* const* d_in, const int* in_sizes, int n_in,
                              void* d_out, int out_size) {
    const float* feat = (const float*)d_in[0];
    const float* rois = (const float*)d_in[1];
    const float* w1   = (const float*)d_in[2];
    const float* b1   = (const float*)d_in[3];
    const float* w2   = (const float*)d_in[4];
    const float* b2   = (const float*)d_in[5];
    const float* w3   = (const float*)d_in[6];
    const float* b3   = (const float*)d_in[7];
    float* out = (float*)d_out;

    static float *pX=nullptr, *pH1=nullptr, *pH2=nullptr, *pOM=nullptr, *pPart=nullptr;
    if (!pX) {
        void* p;
        cudaGetSymbolAddress(&p, g_X);    pX    = (float*)p;
        cudaGetSymbolAddress(&p, g_H1);   pH1   = (float*)p;
        cudaGetSymbolAddress(&p, g_H2);   pH2   = (float*)p;
        cudaGetSymbolAddress(&p, g_OM);   pOM   = (float*)p;
        cudaGetSymbolAddress(&p, g_part); pPart = (float*)p;
        cudaFuncSetAttribute(fcmma_kernel<K1,  DFC, DFC, 9>,
                             cudaFuncAttributeMaxDynamicSharedMemorySize, GEMM_SMEM_BYTES);
        cudaFuncSetAttribute(fcmma_kernel<DFC, DFC, DFC, 8>,
                             cudaFuncAttributeMaxDynamicSharedMemorySize, GEMM_SMEM_BYTES);
        cudaFuncSetAttribute(fcmma_kernel<DFC, M3,  256, 32>,
                             cudaFuncAttributeMaxDynamicSharedMemorySize, GEMM_SMEM_BYTES);
        cudaFuncSetAttribute(layout_fix_kernel,
                             cudaFuncAttributeMaxDynamicSharedMemorySize, FIX_SMEM);
    }

    // 1. NCHW -> NHWC
    dim3 tb(32, 8);
    dim3 tg((HH*WW + 31) / 32, CC / 32, NB);
    transpose_kernel<<<tg, tb>>>(feat);

    // 2. pool (no offsets) -> staging -> g_X (tf32-rounded, coalesced)
    pool_meta_kernel<false><<<(NBIN + 255) / 256, 256>>>(rois);
    pool_gather_kernel<false><<<NBIN / 4, 256>>>();
    layout_fix_kernel<<<NROI, 256, FIX_SMEM>>>(pX);

    // 3. FC stack: split-K TF32 mma.sync (128x256, 64x64 warp tiles) + fused reduce
    fcmma_kernel<K1,  DFC, DFC, 9><<<dim3(DFC/BN, NROI/BM, 9), 256, GEMM_SMEM_BYTES>>>(pX,  w1, pPart);
    reduce_vec_kernel<DFC, DFC, 9, true, true><<<(NROI*DFC/4 + 255)/256, 256>>>(pPart, b1, pH1);

    fcmma_kernel<DFC, DFC, DFC, 8><<<dim3(DFC/BN, NROI/BM, 8), 256, GEMM_SMEM_BYTES>>>(pH1, w2, pPart);
    reduce_vec_kernel<DFC, DFC, 8, true, true><<<(NROI*DFC/4 + 255)/256, 256>>>(pPart, b2, pH2);

    fcmma_kernel<DFC, M3, 256, 32><<<dim3(1, NROI/BM, 32), 256, GEMM_SMEM_BYTES>>>(pH2, w3, pPart);
    reduce_kernel<M3, 256, 32, false><<<(NROI*M3 + 255)/256, 256>>>(pPart, b3, pOM);

    // 4. deformable pool with offsets (+mask) -> staging -> out (coalesced)
    pool_meta_kernel<true><<<(NBIN + 255) / 256, 256>>>(rois);
    pool_gather_kernel<true><<<NBIN / 4, 256>>>();
    layout_fix_kernel<<<NROI, 256, FIX_SMEM>>>(out);
}

// round 11
// speedup vs baseline: 1.9225x; 1.0275x over previous
#include <cuda_runtime.h>
#include <math.h>
#include <stdint.h>

// ---------------- problem constants ----------------
#define NB 2
#define CC 256
#define HH 100
#define WW 100
#define NROI 512
#define PP 7
#define SS 4
#define SCALEF 0.0625f
#define TRANS_STDF 0.1f
#define K1 (CC*PP*PP)     // 12544
#define DFC 1024
#define M3 (PP*PP*3)      // 147

// ---------------- scratch (device globals; no allocs allowed) ----------------
__device__ float g_featT[NB*HH*WW*CC];   // NHWC features
__device__ float g_X[NROI*K1];           // pooled (no-trans) features (tf32-rounded)
__device__ float g_H1[NROI*DFC];
__device__ float g_H2[NROI*DFC];
__device__ float g_OM[NROI*M3];          // offsets (2*49) + mask logit (49)
__device__ float g_part[9*NROI*DFC];     // split-K partials (18.9 MB)

// ======================= small PTX helpers (sm_80+ baseline only) =======================
__device__ __forceinline__ uint32_t smem_u32(const void* p) {
    uint32_t a;
    asm("{ .reg .u64 t; cvta.to.shared.u64 t, %1; cvt.u32.u64 %0, t; }"
        : "=r"(a) : "l"(p));
    return a;
}

__device__ __forceinline__ void cpasync16(uint32_t dst, const void* src, bool pred) {
    int sz = pred ? 16 : 0;
    asm volatile("cp.async.cg.shared.global [%0], [%1], 16, %2;"
                 :: "r"(dst), "l"(src), "r"(sz) : "memory");
}

__device__ __forceinline__ uint32_t f2tf32(float f) {
    uint32_t u;
    asm("cvt.rna.tf32.f32 %0, %1;" : "=r"(u) : "f"(f));
    return u;
}

__device__ __forceinline__ float roundtf32(float f) {
    return __uint_as_float(f2tf32(f));
}

__device__ __forceinline__ void mma_tf32(float c[4], const uint32_t a[4], const uint32_t b[2]) {
    asm volatile(
        "mma.sync.aligned.m16n8k8.row.col.f32.tf32.tf32.f32 "
        "{%0,%1,%2,%3}, {%4,%5,%6,%7}, {%8,%9}, {%0,%1,%2,%3};"
        : "+f"(c[0]), "+f"(c[1]), "+f"(c[2]), "+f"(c[3])
        : "r"(a[0]), "r"(a[1]), "r"(a[2]), "r"(a[3]), "r"(b[0]), "r"(b[1]));
}

// ---------------- NCHW -> NHWC transpose ----------------
__global__ void transpose_kernel(const float* __restrict__ feat) {
    __shared__ float tile[32][33];
    int b   = blockIdx.z;
    int hw0 = blockIdx.x * 32;
    int c0  = blockIdx.y * 32;
    int tx = threadIdx.x, ty = threadIdx.y; // (32, 8)
    const float* src = feat + (size_t)b * CC * HH * WW;
    float* dst = g_featT + (size_t)b * HH * WW * CC;
    #pragma unroll
    for (int j = 0; j < 32; j += 8) {
        int c  = c0 + ty + j;
        int hw = hw0 + tx;
        tile[ty + j][tx] = (hw < HH*WW) ? src[c * (HH*WW) + hw] : 0.0f;
    }
    __syncthreads();
    #pragma unroll
    for (int j = 0; j < 32; j += 8) {
        int hw = hw0 + ty + j;
        int c  = c0 + tx;
        if (hw < HH*WW) dst[hw * CC + c] = tile[tx][ty + j];
    }
}

// ================= fused deformable PSROI pool: one block per ROI =================
// stage 1: threads 0..48 compute per-bin metadata (weights/mask/origin) into smem
// stage 2: 49 bins x 64 channel-quads striped over 512 threads, float4 gathers
// stage 3: coalesced write of the 12544-float row in (c*49+pp) layout
#define VPITCH 260
#define FUSED_SMEM ((49*VPITCH + 49*41) * 4)   // 58996 B

template<bool TRANS>
__global__ void __launch_bounds__(512) pool_fused_kernel(const float* __restrict__ rois,
                                                         float* __restrict__ dstbuf) {
    extern __shared__ float sg[];
    float* vals  = sg;              // [49 pp][VPITCH], c contiguous
    float* smeta = sg + 49*VPITCH;  // [49 pp][41]

    int n   = blockIdx.x;
    int tid = threadIdx.x;

    // ---- stage 1: metadata for 49 bins ----
    if (tid < 49) {
        int pp = tid;
        int ph = pp / 7, pw = pp % 7;
        float* wg = smeta + pp * 41;
        #pragma unroll
        for (int i = 0; i < 36; i++) wg[i] = 0.0f;

        const float* r = rois + n * 5;
        int b = (int)r[0];
        float rsw = rintf(r[1]) * SCALEF - 0.5f;
        float rsh = rintf(r[2]) * SCALEF - 0.5f;
        float rew = (rintf(r[3]) + 1.0f) * SCALEF - 0.5f;
        float reh = (rintf(r[4]) + 1.0f) * SCALEF - 0.5f;
        float roi_w = fmaxf(rew - rsw, 0.1f);
        float roi_h = fmaxf(reh - rsh, 0.1f);
        float bin_h = roi_h / (float)PP;
        float bin_w = roi_w / (float)PP;
        float sub_h = bin_h / (float)SS;
        float sub_w = bin_w / (float)SS;

        float tx_ = 0.0f, ty_ = 0.0f, mask = 1.0f;
        if (TRANS) {
            int part_h = (int)floorf((float)ph / (float)PP * 7.0f);
            int part_w = (int)floorf((float)pw / (float)PP * 7.0f);
            const float* o = g_OM + n * M3;
            tx_ = o[0*49 + part_h*7 + part_w] * TRANS_STDF;
            ty_ = o[1*49 + part_h*7 + part_w] * TRANS_STDF;
            float ml = o[2*49 + pp];
            mask = 1.0f / (1.0f + expf(-ml));
        }
        float hstart = (float)ph * bin_h + rsh + ty_ * roi_h;
        float wstart = (float)pw * bin_w + rsw + tx_ * roi_w;

        int horg = (int)floorf(fminf(fmaxf(hstart, 0.0f), (float)(HH-1)));
        int worg = (int)floorf(fminf(fmaxf(wstart, 0.0f), (float)(WW-1)));
        int cnt = 0;
        #pragma unroll
        for (int iy = 0; iy < SS; iy++) {
            float h = hstart + (float)iy * sub_h;
            #pragma unroll
            for (int ix = 0; ix < SS; ix++) {
                float w = wstart + (float)ix * sub_w;
                bool valid = (w >= -0.5f) && (w <= (float)WW - 0.5f) &&
                             (h >= -0.5f) && (h <= (float)HH - 0.5f);
                if (!valid) continue;
                cnt++;
                float hc = fminf(fmaxf(h, 0.0f), (float)(HH-1));
                float wc = fminf(fmaxf(w, 0.0f), (float)(WW-1));
                int h0 = (int)floorf(hc), w0 = (int)floorf(wc);
                int h1 = min(h0 + 1, HH - 1), w1 = min(w0 + 1, WW - 1);
                float lh = hc - (float)h0, lw = wc - (float)w0;
                int r0 = min(max(h0 - horg, 0), 5);
                int r1 = min(max(h1 - horg, 0), 5);
                int c0 = min(max(w0 - worg, 0), 5);
                int c1 = min(max(w1 - worg, 0), 5);
                wg[r0*6 + c0] += (1.0f - lh) * (1.0f - lw);
                wg[r0*6 + c1] += (1.0f - lh) * lw;
                wg[r1*6 + c0] += lh * (1.0f - lw);
                wg[r1*6 + c1] += lh * lw;
            }
        }
        float invc = (cnt > 0) ? (1.0f / (float)cnt) : 0.0f;
        float scale = invc * (TRANS ? mask : 1.0f);
        #pragma unroll
        for (int i = 0; i < 36; i++) wg[i] *= scale;   // fold 1/cnt (and mask) in
        wg[38] = __int_as_float(horg);
        wg[39] = __int_as_float(worg);
        wg[40] = __int_as_float(b * HH * WW * CC);
    }
    __syncthreads();

    // ---- stage 2: gather 49 bins x 64 quads ----
    #pragma unroll 1
    for (int t = tid; t < 49 * 64; t += 512) {
        int bin  = t >> 6;
        int quad = t & 63;
        const float* m = smeta + bin * 41;
        int horg = __float_as_int(m[38]);
        int worg = __float_as_int(m[39]);
        int base = __float_as_int(m[40]);

        float4 acc = make_float4(0.f, 0.f, 0.f, 0.f);
        #pragma unroll
        for (int cell = 0; cell < 36; cell++) {
            float wt = m[cell];
            if (wt != 0.0f) {
                int y = min(horg + cell / 6, HH - 1);
                int x = min(worg + cell % 6, WW - 1);
                float4 f = *reinterpret_cast<const float4*>(
                    g_featT + base + (y * WW + x) * CC + quad * 4);
                acc.x += wt * f.x; acc.y += wt * f.y;
                acc.z += wt * f.z; acc.w += wt * f.w;
            }
        }
        if (!TRANS) {
            acc.x = roundtf32(acc.x); acc.y = roundtf32(acc.y);
            acc.z = roundtf32(acc.z); acc.w = roundtf32(acc.w);
        }
        *reinterpret_cast<float4*>(vals + bin * VPITCH + quad * 4) = acc;
    }
    __syncthreads();

    // ---- stage 3: coalesced output in (c*49+pp) layout ----
    // K1 = 12544 is NOT a multiple of 512: guarded stride loop (25 iters, last partial)
    float* dst = dstbuf + (size_t)n * K1;
    #pragma unroll 1
    for (int k = tid; k < K1; k += 512) {
        int c = k / 49, pp = k - c * 49;
        dst[k] = vals[pp * VPITCH + c];
    }
}

// ============ TF32 mma.sync GEMM, split-K, BM=128 x BN=256, 8 warps x 64x64 ============
#define BM 128
#define BN 256
#define BK 32
#define GPAD 36
#define GSTAGES 4
#define ASZ (BM*GPAD)
#define BSZ (BN*GPAD)
#define STGSZ (ASZ+BSZ)
#define GEMM_SMEM_BYTES (GSTAGES*STGSZ*4)   // 221184 B

template<int KDIM, int JROWS, int JS, int SPLITK>
__global__ void __launch_bounds__(256) fcmma_kernel(
    const float* __restrict__ A, const float* __restrict__ Wt,
    float* __restrict__ Part)
{
    static_assert(KDIM % BK == 0, "K multiple of BK");
    constexpr int KT = KDIM / BK;
    constexpr int CH = (KT + SPLITK - 1) / SPLITK;

    extern __shared__ float sm[];
    int tid  = threadIdx.x;
    int lane = tid & 31, wid = tid >> 5;
    int m0 = blockIdx.y * BM, n0 = blockIdx.x * BN;
    int z  = blockIdx.z;
    int t0 = z * CH;
    int ntc = min(KT - t0, CH);

    int g = lane >> 2, tg = lane & 3;
    int wm = (wid & 1) * 64;
    int wn = (wid >> 1) * 64;

    float c[4][8][4];
    #pragma unroll
    for (int mt = 0; mt < 4; mt++)
        #pragma unroll
        for (int nt = 0; nt < 8; nt++)
            #pragma unroll
            for (int q = 0; q < 4; q++) c[mt][nt][q] = 0.0f;

    int lrow = tid >> 3;
    int lchk = tid & 7;

    auto load_stage = [&](int s, int t) {
        float* As = sm + s * STGSZ;
        float* Bs = As + ASZ;
        int kg = t * BK + lchk * 4;
        #pragma unroll
        for (int it = 0; it < 4; it++) {
            int r = lrow + it * 32;
            cpasync16(smem_u32(As + r * GPAD + lchk * 4),
                      A + (size_t)(m0 + r) * KDIM + kg, true);
        }
        #pragma unroll
        for (int it = 0; it < 8; it++) {
            int r = lrow + it * 32;
            int br = n0 + r;
            bool ok = ((JROWS % BN) == 0) || (br < JROWS);
            cpasync16(smem_u32(Bs + r * GPAD + lchk * 4),
                      Wt + (size_t)(ok ? br : 0) * KDIM + kg, ok);
        }
    };

    #pragma unroll
    for (int s = 0; s < GSTAGES - 1; s++) {
        if (s < ntc) load_stage(s, t0 + s);
        asm volatile("cp.async.commit_group;" ::: "memory");
    }

    #pragma unroll 1
    for (int i = 0; i < ntc; i++) {
        asm volatile("cp.async.wait_group %0;" :: "n"(GSTAGES - 2) : "memory");
        __syncthreads();

        int tn = i + GSTAGES - 1;
        if (tn < ntc) load_stage(tn % GSTAGES, t0 + tn);
        asm volatile("cp.async.commit_group;" ::: "memory");

        const float* As = sm + (i % GSTAGES) * STGSZ;
        const float* Bs = As + ASZ;
        #pragma unroll
        for (int ks = 0; ks < 4; ks++) {
            int kk = ks * 8;
            uint32_t a[4][4], b[8][2];
            #pragma unroll
            for (int mt = 0; mt < 4; mt++) {
                int m = wm + mt * 16 + g;
                a[mt][0] = __float_as_uint(As[m * GPAD + kk + tg]);
                a[mt][1] = __float_as_uint(As[(m + 8) * GPAD + kk + tg]);
                a[mt][2] = __float_as_uint(As[m * GPAD + kk + tg + 4]);
                a[mt][3] = __float_as_uint(As[(m + 8) * GPAD + kk + tg + 4]);
            }
            #pragma unroll
            for (int nt = 0; nt < 8; nt++) {
                int nn = wn + nt * 8 + g;
                b[nt][0] = f2tf32(Bs[nn * GPAD + kk + tg]);
                b[nt][1] = f2tf32(Bs[nn * GPAD + kk + tg + 4]);
            }
            #pragma unroll
            for (int mt = 0; mt < 4; mt++)
                #pragma unroll
                for (int nt = 0; nt < 8; nt++)
                    mma_tf32(c[mt][nt], a[mt], b[nt]);
        }
        __syncthreads();
    }

    float* P = Part + (size_t)z * NROI * JS;
    #pragma unroll
    for (int mt = 0; mt < 4; mt++) {
        int row0 = m0 + wm + mt * 16 + g;
        #pragma unroll
        for (int nt = 0; nt < 8; nt++) {
            int j0 = n0 + wn + nt * 8 + tg * 2;
            #pragma unroll
            for (int h = 0; h < 2; h++) {
                int row = row0 + h * 8;
                float2 v = make_float2(c[mt][nt][h*2], c[mt][nt][h*2+1]);
                *reinterpret_cast<float2*>(P + (size_t)row * JS + j0) = v;
            }
        }
    }
}

// vectorized reduce: partials + bias + relu (+ tf32 round for next GEMM)
template<int J, int JS, int SPLITK, bool RELU, bool ROUND>
__global__ void __launch_bounds__(256) reduce_vec_kernel(
    const float* __restrict__ Part, const float* __restrict__ bias,
    float* __restrict__ Cout)
{
    int idx = blockIdx.x * 256 + threadIdx.x;
    if (idx >= NROI * (J / 4)) return;
    int row = idx / (J / 4), jv = idx - row * (J / 4);
    int j = jv * 4;
    float4 v = make_float4(0.f, 0.f, 0.f, 0.f);
    #pragma unroll
    for (int z = 0; z < SPLITK; z++) {
        float4 p = *reinterpret_cast<const float4*>(Part + ((size_t)z * NROI + row) * JS + j);
        v.x += p.x; v.y += p.y; v.z += p.z; v.w += p.w;
    }
    float4 bb = *reinterpret_cast<const float4*>(bias + j);
    v.x += bb.x; v.y += bb.y; v.z += bb.z; v.w += bb.w;
    if (RELU) {
        v.x = fmaxf(v.x, 0.f); v.y = fmaxf(v.y, 0.f);
        v.z = fmaxf(v.z, 0.f); v.w = fmaxf(v.w, 0.f);
    }
    if (ROUND) {
        v.x = roundtf32(v.x); v.y = roundtf32(v.y);
        v.z = roundtf32(v.z); v.w = roundtf32(v.w);
    }
    *reinterpret_cast<float4*>(Cout + (size_t)row * J + j) = v;
}

template<int J, int JS, int SPLITK, bool RELU>
__global__ void __launch_bounds__(256) reduce_kernel(
    const float* __restrict__ Part, const float* __restrict__ bias,
    float* __restrict__ Cout)
{
    int idx = blockIdx.x * 256 + threadIdx.x;
    if (idx >= NROI * J) return;
    int row = idx / J, j = idx - row * J;
    float v = 0.0f;
    #pragma unroll
    for (int z = 0; z < SPLITK; z++)
        v += Part[((size_t)z * NROI + row) * JS + j];
    v += __ldg(bias + j);
    if (RELU) v = fmaxf(v, 0.0f);
    Cout[idx] = v;
}

// ======================= launch =======================
extern "C" void kernel_launch(void* const* d_in, const int* in_sizes, int n_in,
                              void* d_out, int out_size) {
    const float* feat = (const float*)d_in[0];
    const float* rois = (const float*)d_in[1];
    const float* w1   = (const float*)d_in[2];
    const float* b1   = (const float*)d_in[3];
    const float* w2   = (const float*)d_in[4];
    const float* b2   = (const float*)d_in[5];
    const float* w3   = (const float*)d_in[6];
    const float* b3   = (const float*)d_in[7];
    float* out = (float*)d_out;

    static float *pX=nullptr, *pH1=nullptr, *pH2=nullptr, *pOM=nullptr, *pPart=nullptr;
    if (!pX) {
        void* p;
        cudaGetSymbolAddress(&p, g_X);    pX    = (float*)p;
        cudaGetSymbolAddress(&p, g_H1);   pH1   = (float*)p;
        cudaGetSymbolAddress(&p, g_H2);   pH2   = (float*)p;
        cudaGetSymbolAddress(&p, g_OM);   pOM   = (float*)p;
        cudaGetSymbolAddress(&p, g_part); pPart = (float*)p;
        cudaFuncSetAttribute(fcmma_kernel<K1,  DFC, DFC, 9>,
                             cudaFuncAttributeMaxDynamicSharedMemorySize, GEMM_SMEM_BYTES);
        cudaFuncSetAttribute(fcmma_kernel<DFC, DFC, DFC, 8>,
                             cudaFuncAttributeMaxDynamicSharedMemorySize, GEMM_SMEM_BYTES);
        cudaFuncSetAttribute(fcmma_kernel<DFC, M3,  256, 32>,
                             cudaFuncAttributeMaxDynamicSharedMemorySize, GEMM_SMEM_BYTES);
        cudaFuncSetAttribute(pool_fused_kernel<false>,
                             cudaFuncAttributeMaxDynamicSharedMemorySize, FUSED_SMEM);
        cudaFuncSetAttribute(pool_fused_kernel<true>,
                             cudaFuncAttributeMaxDynamicSharedMemorySize, FUSED_SMEM);
    }

    // 1. NCHW -> NHWC
    dim3 tb(32, 8);
    dim3 tg((HH*WW + 31) / 32, CC / 32, NB);
    transpose_kernel<<<tg, tb>>>(feat);

    // 2. fused pool (no offsets) -> g_X (tf32-rounded, coalesced)
    pool_fused_kernel<false><<<NROI, 512, FUSED_SMEM>>>(rois, pX);

    // 3. FC stack: split-K TF32 mma.sync (128x256, 64x64 warp tiles) + fused reduce
    fcmma_kernel<K1,  DFC, DFC, 9><<<dim3(DFC/BN, NROI/BM, 9), 256, GEMM_SMEM_BYTES>>>(pX,  w1, pPart);
    reduce_vec_kernel<DFC, DFC, 9, true, true><<<(NROI*DFC/4 + 255)/256, 256>>>(pPart, b1, pH1);

    fcmma_kernel<DFC, DFC, DFC, 8><<<dim3(DFC/BN, NROI/BM, 8), 256, GEMM_SMEM_BYTES>>>(pH1, w2, pPart);
    reduce_vec_kernel<DFC, DFC, 8, true, true><<<(NROI*DFC/4 + 255)/256, 256>>>(pPart, b2, pH2);

    fcmma_kernel<DFC, M3, 256, 32><<<dim3(1, NROI/BM, 32), 256, GEMM_SMEM_BYTES>>>(pH2, w3, pPart);
    reduce_kernel<M3, 256, 32, false><<<(NROI*M3 + 255)/256, 256>>>(pPart, b3, pOM);

    // 4. fused deformable pool with offsets (+mask) -> out (coalesced)
    pool_fused_kernel<true><<<NROI, 512, FUSED_SMEM>>>(rois, out);
}

// round 12
// speedup vs baseline: 1.9261x; 1.0019x over previous
#include <cuda_runtime.h>
#include <math.h>
#include <stdint.h>

// ---------------- problem constants ----------------
#define NB 2
#define CC 256
#define HH 100
#define WW 100
#define NROI 512
#define PP 7
#define SS 4
#define SCALEF 0.0625f
#define TRANS_STDF 0.1f
#define K1 (CC*PP*PP)     // 12544
#define DFC 1024
#define M3 (PP*PP*3)      // 147

// ---------------- scratch (device globals; no allocs allowed) ----------------
__device__ float g_featT[NB*HH*WW*CC];   // NHWC features
__device__ float g_X[NROI*K1];           // pooled (no-trans) features (tf32-rounded)
__device__ float g_H1[NROI*DFC];
__device__ float g_H2[NROI*DFC];
__device__ float g_part[9*NROI*DFC];     // split-K partials (18.9 MB)

// ======================= small PTX helpers (sm_80+ baseline only) =======================
__device__ __forceinline__ uint32_t smem_u32(const void* p) {
    uint32_t a;
    asm("{ .reg .u64 t; cvta.to.shared.u64 t, %1; cvt.u32.u64 %0, t; }"
        : "=r"(a) : "l"(p));
    return a;
}

__device__ __forceinline__ void cpasync16(uint32_t dst, const void* src, bool pred) {
    int sz = pred ? 16 : 0;
    asm volatile("cp.async.cg.shared.global [%0], [%1], 16, %2;"
                 :: "r"(dst), "l"(src), "r"(sz) : "memory");
}

__device__ __forceinline__ uint32_t f2tf32(float f) {
    uint32_t u;
    asm("cvt.rna.tf32.f32 %0, %1;" : "=r"(u) : "f"(f));
    return u;
}

__device__ __forceinline__ float roundtf32(float f) {
    return __uint_as_float(f2tf32(f));
}

__device__ __forceinline__ void mma_tf32(float c[4], const uint32_t a[4], const uint32_t b[2]) {
    asm volatile(
        "mma.sync.aligned.m16n8k8.row.col.f32.tf32.tf32.f32 "
        "{%0,%1,%2,%3}, {%4,%5,%6,%7}, {%8,%9}, {%0,%1,%2,%3};"
        : "+f"(c[0]), "+f"(c[1]), "+f"(c[2]), "+f"(c[3])
        : "r"(a[0]), "r"(a[1]), "r"(a[2]), "r"(a[3]), "r"(b[0]), "r"(b[1]));
}

// ---------------- NCHW -> NHWC transpose ----------------
__global__ void transpose_kernel(const float* __restrict__ feat) {
    __shared__ float tile[32][33];
    int b   = blockIdx.z;
    int hw0 = blockIdx.x * 32;
    int c0  = blockIdx.y * 32;
    int tx = threadIdx.x, ty = threadIdx.y; // (32, 8)
    const float* src = feat + (size_t)b * CC * HH * WW;
    float* dst = g_featT + (size_t)b * HH * WW * CC;
    #pragma unroll
    for (int j = 0; j < 32; j += 8) {
        int c  = c0 + ty + j;
        int hw = hw0 + tx;
        tile[ty + j][tx] = (hw < HH*WW) ? src[c * (HH*WW) + hw] : 0.0f;
    }
    __syncthreads();
    #pragma unroll
    for (int j = 0; j < 32; j += 8) {
        int hw = hw0 + ty + j;
        int c  = c0 + tx;
        if (hw < HH*WW) dst[hw * CC + c] = tile[tx][ty + j];
    }
}

// ================= fused deformable PSROI pool: one block per ROI =================
// stage 0 (TRANS only): reduce FC3 split-K partials + bias -> om[147] in smem
// stage 1: threads 0..48 compute per-bin metadata (weights/mask/origin) into smem
// stage 2: 49 bins x 64 channel-quads striped over 512 threads, float4 gathers
// stage 3: coalesced write of the 12544-float row in (c*49+pp) layout
#define VPITCH 260
#define FC3_SPLITK 32
#define FUSED_SMEM ((49*VPITCH + 49*41 + 148) * 4)

template<bool TRANS>
__global__ void __launch_bounds__(512) pool_fused_kernel(const float* __restrict__ rois,
                                                         const float* __restrict__ Part,
                                                         const float* __restrict__ bias3,
                                                         float* __restrict__ dstbuf) {
    extern __shared__ float sg[];
    float* vals  = sg;                       // [49 pp][VPITCH], c contiguous
    float* smeta = sg + 49*VPITCH;           // [49 pp][41]
    float* som   = sg + 49*VPITCH + 49*41;   // [147] offsets+mask logits

    int n   = blockIdx.x;
    int tid = threadIdx.x;

    // ---- stage 0: fold FC3 split-K reduce into this kernel ----
    if (TRANS) {
        if (tid < M3) {
            float s = 0.0f;
            #pragma unroll
            for (int z = 0; z < FC3_SPLITK; z++)
                s += Part[((size_t)z * NROI + n) * 256 + tid];
            som[tid] = s + bias3[tid];
        }
        __syncthreads();
    }

    // ---- stage 1: metadata for 49 bins ----
    if (tid < 49) {
        int pp = tid;
        int ph = pp / 7, pw = pp % 7;
        float* wg = smeta + pp * 41;
        #pragma unroll
        for (int i = 0; i < 36; i++) wg[i] = 0.0f;

        const float* r = rois + n * 5;
        int b = (int)r[0];
        float rsw = rintf(r[1]) * SCALEF - 0.5f;
        float rsh = rintf(r[2]) * SCALEF - 0.5f;
        float rew = (rintf(r[3]) + 1.0f) * SCALEF - 0.5f;
        float reh = (rintf(r[4]) + 1.0f) * SCALEF - 0.5f;
        float roi_w = fmaxf(rew - rsw, 0.1f);
        float roi_h = fmaxf(reh - rsh, 0.1f);
        float bin_h = roi_h / (float)PP;
        float bin_w = roi_w / (float)PP;
        float sub_h = bin_h / (float)SS;
        float sub_w = bin_w / (float)SS;

        float tx_ = 0.0f, ty_ = 0.0f, mask = 1.0f;
        if (TRANS) {
            int part_h = (int)floorf((float)ph / (float)PP * 7.0f);
            int part_w = (int)floorf((float)pw / (float)PP * 7.0f);
            tx_ = som[0*49 + part_h*7 + part_w] * TRANS_STDF;
            ty_ = som[1*49 + part_h*7 + part_w] * TRANS_STDF;
            float ml = som[2*49 + pp];
            mask = 1.0f / (1.0f + expf(-ml));
        }
        float hstart = (float)ph * bin_h + rsh + ty_ * roi_h;
        float wstart = (float)pw * bin_w + rsw + tx_ * roi_w;

        int horg = (int)floorf(fminf(fmaxf(hstart, 0.0f), (float)(HH-1)));
        int worg = (int)floorf(fminf(fmaxf(wstart, 0.0f), (float)(WW-1)));
        int cnt = 0;
        #pragma unroll
        for (int iy = 0; iy < SS; iy++) {
            float h = hstart + (float)iy * sub_h;
            #pragma unroll
            for (int ix = 0; ix < SS; ix++) {
                float w = wstart + (float)ix * sub_w;
                bool valid = (w >= -0.5f) && (w <= (float)WW - 0.5f) &&
                             (h >= -0.5f) && (h <= (float)HH - 0.5f);
                if (!valid) continue;
                cnt++;
                float hc = fminf(fmaxf(h, 0.0f), (float)(HH-1));
                float wc = fminf(fmaxf(w, 0.0f), (float)(WW-1));
                int h0 = (int)floorf(hc), w0 = (int)floorf(wc);
                int h1 = min(h0 + 1, HH - 1), w1 = min(w0 + 1, WW - 1);
                float lh = hc - (float)h0, lw = wc - (float)w0;
                int r0 = min(max(h0 - horg, 0), 5);
                int r1 = min(max(h1 - horg, 0), 5);
                int c0 = min(max(w0 - worg, 0), 5);
                int c1 = min(max(w1 - worg, 0), 5);
                wg[r0*6 + c0] += (1.0f - lh) * (1.0f - lw);
                wg[r0*6 + c1] += (1.0f - lh) * lw;
                wg[r1*6 + c0] += lh * (1.0f - lw);
                wg[r1*6 + c1] += lh * lw;
            }
        }
        float invc = (cnt > 0) ? (1.0f / (float)cnt) : 0.0f;
        float scale = invc * (TRANS ? mask : 1.0f);
        #pragma unroll
        for (int i = 0; i < 36; i++) wg[i] *= scale;   // fold 1/cnt (and mask) in
        wg[38] = __int_as_float(horg);
        wg[39] = __int_as_float(worg);
        wg[40] = __int_as_float(b * HH * WW * CC);
    }
    __syncthreads();

    // ---- stage 2: gather 49 bins x 64 quads ----
    #pragma unroll 1
    for (int t = tid; t < 49 * 64; t += 512) {
        int bin  = t >> 6;
        int quad = t & 63;
        const float* m = smeta + bin * 41;
        int horg = __float_as_int(m[38]);
        int worg = __float_as_int(m[39]);
        int base = __float_as_int(m[40]);

        float4 acc = make_float4(0.f, 0.f, 0.f, 0.f);
        #pragma unroll
        for (int cell = 0; cell < 36; cell++) {
            float wt = m[cell];
            if (wt != 0.0f) {
                int y = min(horg + cell / 6, HH - 1);
                int x = min(worg + cell % 6, WW - 1);
                float4 f = *reinterpret_cast<const float4*>(
                    g_featT + base + (y * WW + x) * CC + quad * 4);
                acc.x += wt * f.x; acc.y += wt * f.y;
                acc.z += wt * f.z; acc.w += wt * f.w;
            }
        }
        if (!TRANS) {
            acc.x = roundtf32(acc.x); acc.y = roundtf32(acc.y);
            acc.z = roundtf32(acc.z); acc.w = roundtf32(acc.w);
        }
        *reinterpret_cast<float4*>(vals + bin * VPITCH + quad * 4) = acc;
    }
    __syncthreads();

    // ---- stage 3: coalesced output in (c*49+pp) layout (guarded: K1 % 512 != 0) ----
    float* dst = dstbuf + (size_t)n * K1;
    #pragma unroll 1
    for (int k = tid; k < K1; k += 512) {
        int c = k / 49, pp = k - c * 49;
        dst[k] = vals[pp * VPITCH + c];
    }
}

// ============ TF32 mma.sync GEMM, split-K, BM=128 x BN=256, 8 warps x 64x64 ============
// Single-sync multistage: the barrier after wait_group also protects stage reuse,
// because load_stage(i) targets stage (i+3)%4 == (i-1)%4, whose readers all finished
// before the iter-i barrier.
#define BM 128
#define BN 256
#define BK 32
#define GPAD 36
#define GSTAGES 4
#define ASZ (BM*GPAD)
#define BSZ (BN*GPAD)
#define STGSZ (ASZ+BSZ)
#define GEMM_SMEM_BYTES (GSTAGES*STGSZ*4)   // 221184 B

template<int KDIM, int JROWS, int JS, int SPLITK>
__global__ void __launch_bounds__(256) fcmma_kernel(
    const float* __restrict__ A, const float* __restrict__ Wt,
    float* __restrict__ Part)
{
    static_assert(KDIM % BK == 0, "K multiple of BK");
    constexpr int KT = KDIM / BK;
    constexpr int CH = (KT + SPLITK - 1) / SPLITK;

    extern __shared__ float sm[];
    int tid  = threadIdx.x;
    int lane = tid & 31, wid = tid >> 5;
    int m0 = blockIdx.y * BM, n0 = blockIdx.x * BN;
    int z  = blockIdx.z;
    int t0 = z * CH;
    int ntc = min(KT - t0, CH);

    int g = lane >> 2, tg = lane & 3;
    int wm = (wid & 1) * 64;
    int wn = (wid >> 1) * 64;

    float c[4][8][4];
    #pragma unroll
    for (int mt = 0; mt < 4; mt++)
        #pragma unroll
        for (int nt = 0; nt < 8; nt++)
            #pragma unroll
            for (int q = 0; q < 4; q++) c[mt][nt][q] = 0.0f;

    int lrow = tid >> 3;
    int lchk = tid & 7;

    auto load_stage = [&](int s, int t) {
        float* As = sm + s * STGSZ;
        float* Bs = As + ASZ;
        int kg = t * BK + lchk * 4;
        #pragma unroll
        for (int it = 0; it < 4; it++) {
            int r = lrow + it * 32;
            cpasync16(smem_u32(As + r * GPAD + lchk * 4),
                      A + (size_t)(m0 + r) * KDIM + kg, true);
        }
        #pragma unroll
        for (int it = 0; it < 8; it++) {
            int r = lrow + it * 32;
            int br = n0 + r;
            bool ok = ((JROWS % BN) == 0) || (br < JROWS);
            cpasync16(smem_u32(Bs + r * GPAD + lchk * 4),
                      Wt + (size_t)(ok ? br : 0) * KDIM + kg, ok);
        }
    };

    #pragma unroll
    for (int s = 0; s < GSTAGES - 1; s++) {
        if (s < ntc) load_stage(s, t0 + s);
        asm volatile("cp.async.commit_group;" ::: "memory");
    }

    #pragma unroll 1
    for (int i = 0; i < ntc; i++) {
        asm volatile("cp.async.wait_group %0;" :: "n"(GSTAGES - 2) : "memory");
        __syncthreads();

        int tn = i + GSTAGES - 1;
        if (tn < ntc) load_stage(tn % GSTAGES, t0 + tn);
        asm volatile("cp.async.commit_group;" ::: "memory");

        const float* As = sm + (i % GSTAGES) * STGSZ;
        const float* Bs = As + ASZ;
        #pragma unroll
        for (int ks = 0; ks < 4; ks++) {
            int kk = ks * 8;
            uint32_t a[4][4], b[8][2];
            #pragma unroll
            for (int mt = 0; mt < 4; mt++) {
                int m = wm + mt * 16 + g;
                a[mt][0] = __float_as_uint(As[m * GPAD + kk + tg]);
                a[mt][1] = __float_as_uint(As[(m + 8) * GPAD + kk + tg]);
                a[mt][2] = __float_as_uint(As[m * GPAD + kk + tg + 4]);
                a[mt][3] = __float_as_uint(As[(m + 8) * GPAD + kk + tg + 4]);
            }
            #pragma unroll
            for (int nt = 0; nt < 8; nt++) {
                int nn = wn + nt * 8 + g;
                b[nt][0] = f2tf32(Bs[nn * GPAD + kk + tg]);
                b[nt][1] = f2tf32(Bs[nn * GPAD + kk + tg + 4]);
            }
            #pragma unroll
            for (int mt = 0; mt < 4; mt++)
                #pragma unroll
                for (int nt = 0; nt < 8; nt++)
                    mma_tf32(c[mt][nt], a[mt], b[nt]);
        }
        // no trailing __syncthreads: next iter's barrier (after wait_group)
        // already orders stage reuse.
    }

    float* P = Part + (size_t)z * NROI * JS;
    #pragma unroll
    for (int mt = 0; mt < 4; mt++) {
        int row0 = m0 + wm + mt * 16 + g;
        #pragma unroll
        for (int nt = 0; nt < 8; nt++) {
            int j0 = n0 + wn + nt * 8 + tg * 2;
            #pragma unroll
            for (int h = 0; h < 2; h++) {
                int row = row0 + h * 8;
                float2 v = make_float2(c[mt][nt][h*2], c[mt][nt][h*2+1]);
                *reinterpret_cast<float2*>(P + (size_t)row * JS + j0) = v;
            }
        }
    }
}

// vectorized reduce: partials + bias + relu + tf32 round for next GEMM
template<int J, int JS, int SPLITK, bool RELU, bool ROUND>
__global__ void __launch_bounds__(256) reduce_vec_kernel(
    const float* __restrict__ Part, const float* __restrict__ bias,
    float* __restrict__ Cout)
{
    int idx = blockIdx.x * 256 + threadIdx.x;
    if (idx >= NROI * (J / 4)) return;
    int row = idx / (J / 4), jv = idx - row * (J / 4);
    int j = jv * 4;
    float4 v = make_float4(0.f, 0.f, 0.f, 0.f);
    #pragma unroll
    for (int z = 0; z < SPLITK; z++) {
        float4 p = *reinterpret_cast<const float4*>(Part + ((size_t)z * NROI + row) * JS + j);
        v.x += p.x; v.y += p.y; v.z += p.z; v.w += p.w;
    }
    float4 bb = *reinterpret_cast<const float4*>(bias + j);
    v.x += bb.x; v.y += bb.y; v.z += bb.z; v.w += bb.w;
    if (RELU) {
        v.x = fmaxf(v.x, 0.f); v.y = fmaxf(v.y, 0.f);
        v.z = fmaxf(v.z, 0.f); v.w = fmaxf(v.w, 0.f);
    }
    if (ROUND) {
        v.x = roundtf32(v.x); v.y = roundtf32(v.y);
        v.z = roundtf32(v.z); v.w = roundtf32(v.w);
    }
    *reinterpret_cast<float4*>(Cout + (size_t)row * J + j) = v;
}

// ======================= launch =======================
extern "C" void kernel_launch(void* const* d_in, const int* in_sizes, int n_in,
                              void* d_out, int out_size) {
    const float* feat = (const float*)d_in[0];
    const float* rois = (const float*)d_in[1];
    const float* w1   = (const float*)d_in[2];
    const float* b1   = (const float*)d_in[3];
    const float* w2   = (const float*)d_in[4];
    const float* b2   = (const float*)d_in[5];
    const float* w3   = (const float*)d_in[6];
    const float* b3   = (const float*)d_in[7];
    float* out = (float*)d_out;

    static float *pX=nullptr, *pH1=nullptr, *pH2=nullptr, *pPart=nullptr;
    if (!pX) {
        void* p;
        cudaGetSymbolAddress(&p, g_X);    pX    = (float*)p;
        cudaGetSymbolAddress(&p, g_H1);   pH1   = (float*)p;
        cudaGetSymbolAddress(&p, g_H2);   pH2   = (float*)p;
        cudaGetSymbolAddress(&p, g_part); pPart = (float*)p;
        cudaFuncSetAttribute(fcmma_kernel<K1,  DFC, DFC, 9>,
                             cudaFuncAttributeMaxDynamicSharedMemorySize, GEMM_SMEM_BYTES);
        cudaFuncSetAttribute(fcmma_kernel<DFC, DFC, DFC, 8>,
                             cudaFuncAttributeMaxDynamicSharedMemorySize, GEMM_SMEM_BYTES);
        cudaFuncSetAttribute(fcmma_kernel<DFC, M3,  256, FC3_SPLITK>,
                             cudaFuncAttributeMaxDynamicSharedMemorySize, GEMM_SMEM_BYTES);
        cudaFuncSetAttribute(pool_fused_kernel<false>,
                             cudaFuncAttributeMaxDynamicSharedMemorySize, FUSED_SMEM);
        cudaFuncSetAttribute(pool_fused_kernel<true>,
                             cudaFuncAttributeMaxDynamicSharedMemorySize, FUSED_SMEM);
    }

    // 1. NCHW -> NHWC
    dim3 tb(32, 8);
    dim3 tg((HH*WW + 31) / 32, CC / 32, NB);
    transpose_kernel<<<tg, tb>>>(feat);

    // 2. fused pool (no offsets) -> g_X (tf32-rounded, coalesced)
    pool_fused_kernel<false><<<NROI, 512, FUSED_SMEM>>>(rois, nullptr, nullptr, pX);

    // 3. FC stack: split-K TF32 mma.sync (128x256, 64x64 warp tiles) + fused reduce
    fcmma_kernel<K1,  DFC, DFC, 9><<<dim3(DFC/BN, NROI/BM, 9), 256, GEMM_SMEM_BYTES>>>(pX,  w1, pPart);
    reduce_vec_kernel<DFC, DFC, 9, true, true><<<(NROI*DFC/4 + 255)/256, 256>>>(pPart, b1, pH1);

    fcmma_kernel<DFC, DFC, DFC, 8><<<dim3(DFC/BN, NROI/BM, 8), 256, GEMM_SMEM_BYTES>>>(pH1, w2, pPart);
    reduce_vec_kernel<DFC, DFC, 8, true, true><<<(NROI*DFC/4 + 255)/256, 256>>>(pPart, b2, pH2);

    fcmma_kernel<DFC, M3, 256, FC3_SPLITK><<<dim3(1, NROI/BM, FC3_SPLITK), 256, GEMM_SMEM_BYTES>>>(pH2, w3, pPart);

    // 4. fused deformable pool: FC3 reduce + offsets + mask + gather -> out
    pool_fused_kernel<true><<<NROI, 512, FUSED_SMEM>>>(rois, pPart, b3, out);
}

// round 13
// speedup vs baseline: 2.0747x; 1.0772x over previous
#include <cuda_runtime.h>
#include <cuda_fp16.h>
#include <math.h>
#include <stdint.h>

// ---------------- problem constants ----------------
#define NB 2
#define CC 256
#define HH 100
#define WW 100
#define NROI 512
#define PP 7
#define SS 4
#define SCALEF 0.0625f
#define TRANS_STDF 0.1f
#define K1 (CC*PP*PP)     // 12544
#define DFC 1024
#define M3 (PP*PP*3)      // 147

// ---------------- scratch (device globals; no allocs allowed) ----------------
__device__ float  g_featT[NB*HH*WW*CC];   // NHWC features
__device__ __half g_Xh[NROI*K1];          // pooled features, fp16
__device__ __half g_H1h[NROI*DFC];
__device__ __half g_H2h[NROI*DFC];
__device__ __half g_w1h[DFC*K1];          // fp16 weights (converted per launch)
__device__ __half g_w2h[DFC*DFC];
__device__ __half g_w3h[M3*DFC];
__device__ float  g_part[9*NROI*DFC];     // split-K partials (fp32)

// ======================= small PTX helpers (sm_80+ baseline only) =======================
__device__ __forceinline__ uint32_t smem_u32(const void* p) {
    uint32_t a;
    asm("{ .reg .u64 t; cvta.to.shared.u64 t, %1; cvt.u32.u64 %0, t; }"
        : "=r"(a) : "l"(p));
    return a;
}

__device__ __forceinline__ void cpasync16(uint32_t dst, const void* src, bool pred) {
    int sz = pred ? 16 : 0;
    asm volatile("cp.async.cg.shared.global [%0], [%1], 16, %2;"
                 :: "r"(dst), "l"(src), "r"(sz) : "memory");
}

__device__ __forceinline__ void mma_f16(float c[4], const uint32_t a[4], const uint32_t b[2]) {
    asm volatile(
        "mma.sync.aligned.m16n8k16.row.col.f32.f16.f16.f32 "
        "{%0,%1,%2,%3}, {%4,%5,%6,%7}, {%8,%9}, {%0,%1,%2,%3};"
        : "+f"(c[0]), "+f"(c[1]), "+f"(c[2]), "+f"(c[3])
        : "r"(a[0]), "r"(a[1]), "r"(a[2]), "r"(a[3]), "r"(b[0]), "r"(b[1]));
}

// ---------------- fp32 -> fp16 weight conversion (per launch, deterministic) ----------------
__global__ void __launch_bounds__(256) cvt_half_kernel(const float* __restrict__ src,
                                                       __half* __restrict__ dst, int n4) {
    int i = blockIdx.x * 256 + threadIdx.x;
    if (i >= n4) return;
    float4 v = reinterpret_cast<const float4*>(src)[i];
    __half2 h0 = __floats2half2_rn(v.x, v.y);
    __half2 h1 = __floats2half2_rn(v.z, v.w);
    reinterpret_cast<__half2*>(dst)[i*2]     = h0;
    reinterpret_cast<__half2*>(dst)[i*2 + 1] = h1;
}

// ---------------- NCHW -> NHWC transpose ----------------
__global__ void transpose_kernel(const float* __restrict__ feat) {
    __shared__ float tile[32][33];
    int b   = blockIdx.z;
    int hw0 = blockIdx.x * 32;
    int c0  = blockIdx.y * 32;
    int tx = threadIdx.x, ty = threadIdx.y; // (32, 8)
    const float* src = feat + (size_t)b * CC * HH * WW;
    float* dst = g_featT + (size_t)b * HH * WW * CC;
    #pragma unroll
    for (int j = 0; j < 32; j += 8) {
        int c  = c0 + ty + j;
        int hw = hw0 + tx;
        tile[ty + j][tx] = (hw < HH*WW) ? src[c * (HH*WW) + hw] : 0.0f;
    }
    __syncthreads();
    #pragma unroll
    for (int j = 0; j < 32; j += 8) {
        int hw = hw0 + ty + j;
        int c  = c0 + tx;
        if (hw < HH*WW) dst[hw * CC + c] = tile[tx][ty + j];
    }
}

// ================= fused deformable PSROI pool: one block per ROI =================
// stage 0 (TRANS only): reduce FC3 split-K partials + bias -> om[147] in smem
// stage 1: threads 0..48 compute per-bin metadata (weights/mask/origin) into smem
// stage 2: 49 bins x 64 channel-quads striped over 512 threads, float4 gathers
// stage 3: coalesced write of the 12544 row in (c*49+pp) layout (fp16 or fp32)
#define VPITCH 260
#define FC3_SPLITK 32
#define FUSED_SMEM ((49*VPITCH + 49*41 + 148) * 4)

template<bool TRANS>
__global__ void __launch_bounds__(512) pool_fused_kernel(const float* __restrict__ rois,
                                                         const float* __restrict__ Part,
                                                         const float* __restrict__ bias3,
                                                         void* __restrict__ dstbuf) {
    extern __shared__ float sg[];
    float* vals  = sg;                       // [49 pp][VPITCH], c contiguous
    float* smeta = sg + 49*VPITCH;           // [49 pp][41]
    float* som   = sg + 49*VPITCH + 49*41;   // [147] offsets+mask logits

    int n   = blockIdx.x;
    int tid = threadIdx.x;

    // ---- stage 0: fold FC3 split-K reduce into this kernel ----
    if (TRANS) {
        if (tid < M3) {
            float s = 0.0f;
            #pragma unroll
            for (int z = 0; z < FC3_SPLITK; z++)
                s += Part[((size_t)z * NROI + n) * 256 + tid];
            som[tid] = s + bias3[tid];
        }
        __syncthreads();
    }

    // ---- stage 1: metadata for 49 bins ----
    if (tid < 49) {
        int pp = tid;
        int ph = pp / 7, pw = pp % 7;
        float* wg = smeta + pp * 41;
        #pragma unroll
        for (int i = 0; i < 36; i++) wg[i] = 0.0f;

        const float* r = rois + n * 5;
        int b = (int)r[0];
        float rsw = rintf(r[1]) * SCALEF - 0.5f;
        float rsh = rintf(r[2]) * SCALEF - 0.5f;
        float rew = (rintf(r[3]) + 1.0f) * SCALEF - 0.5f;
        float reh = (rintf(r[4]) + 1.0f) * SCALEF - 0.5f;
        float roi_w = fmaxf(rew - rsw, 0.1f);
        float roi_h = fmaxf(reh - rsh, 0.1f);
        float bin_h = roi_h / (float)PP;
        float bin_w = roi_w / (float)PP;
        float sub_h = bin_h / (float)SS;
        float sub_w = bin_w / (float)SS;

        float tx_ = 0.0f, ty_ = 0.0f, mask = 1.0f;
        if (TRANS) {
            int part_h = (int)floorf((float)ph / (float)PP * 7.0f);
            int part_w = (int)floorf((float)pw / (float)PP * 7.0f);
            tx_ = som[0*49 + part_h*7 + part_w] * TRANS_STDF;
            ty_ = som[1*49 + part_h*7 + part_w] * TRANS_STDF;
            float ml = som[2*49 + pp];
            mask = 1.0f / (1.0f + expf(-ml));
        }
        float hstart = (float)ph * bin_h + rsh + ty_ * roi_h;
        float wstart = (float)pw * bin_w + rsw + tx_ * roi_w;

        int horg = (int)floorf(fminf(fmaxf(hstart, 0.0f), (float)(HH-1)));
        int worg = (int)floorf(fminf(fmaxf(wstart, 0.0f), (float)(WW-1)));
        int cnt = 0;
        #pragma unroll
        for (int iy = 0; iy < SS; iy++) {
            float h = hstart + (float)iy * sub_h;
            #pragma unroll
            for (int ix = 0; ix < SS; ix++) {
                float w = wstart + (float)ix * sub_w;
                bool valid = (w >= -0.5f) && (w <= (float)WW - 0.5f) &&
                             (h >= -0.5f) && (h <= (float)HH - 0.5f);
                if (!valid) continue;
                cnt++;
                float hc = fminf(fmaxf(h, 0.0f), (float)(HH-1));
                float wc = fminf(fmaxf(w, 0.0f), (float)(WW-1));
                int h0 = (int)floorf(hc), w0 = (int)floorf(wc);
                int h1 = min(h0 + 1, HH - 1), w1 = min(w0 + 1, WW - 1);
                float lh = hc - (float)h0, lw = wc - (float)w0;
                int r0 = min(max(h0 - horg, 0), 5);
                int r1 = min(max(h1 - horg, 0), 5);
                int c0 = min(max(w0 - worg, 0), 5);
                int c1 = min(max(w1 - worg, 0), 5);
                wg[r0*6 + c0] += (1.0f - lh) * (1.0f - lw);
                wg[r0*6 + c1] += (1.0f - lh) * lw;
                wg[r1*6 + c0] += lh * (1.0f - lw);
                wg[r1*6 + c1] += lh * lw;
            }
        }
        float invc = (cnt > 0) ? (1.0f / (float)cnt) : 0.0f;
        float scale = invc * (TRANS ? mask : 1.0f);
        #pragma unroll
        for (int i = 0; i < 36; i++) wg[i] *= scale;   // fold 1/cnt (and mask) in
        wg[38] = __int_as_float(horg);
        wg[39] = __int_as_float(worg);
        wg[40] = __int_as_float(b * HH * WW * CC);
    }
    __syncthreads();

    // ---- stage 2: gather 49 bins x 64 quads ----
    #pragma unroll 1
    for (int t = tid; t < 49 * 64; t += 512) {
        int bin  = t >> 6;
        int quad = t & 63;
        const float* m = smeta + bin * 41;
        int horg = __float_as_int(m[38]);
        int worg = __float_as_int(m[39]);
        int base = __float_as_int(m[40]);

        float4 acc = make_float4(0.f, 0.f, 0.f, 0.f);
        #pragma unroll
        for (int cell = 0; cell < 36; cell++) {
            float wt = m[cell];
            if (wt != 0.0f) {
                int y = min(horg + cell / 6, HH - 1);
                int x = min(worg + cell % 6, WW - 1);
                float4 f = *reinterpret_cast<const float4*>(
                    g_featT + base + (y * WW + x) * CC + quad * 4);
                acc.x += wt * f.x; acc.y += wt * f.y;
                acc.z += wt * f.z; acc.w += wt * f.w;
            }
        }
        *reinterpret_cast<float4*>(vals + bin * VPITCH + quad * 4) = acc;
    }
    __syncthreads();

    // ---- stage 3: coalesced output in (c*49+pp) layout (guarded: K1 % 512 != 0) ----
    if (TRANS) {
        float* dst = (float*)dstbuf + (size_t)n * K1;
        #pragma unroll 1
        for (int k = tid; k < K1; k += 512) {
            int c = k / 49, pp = k - c * 49;
            dst[k] = vals[pp * VPITCH + c];
        }
    } else {
        __half* dst = (__half*)dstbuf + (size_t)n * K1;
        #pragma unroll 1
        for (int k = tid; k < K1; k += 512) {
            int c = k / 49, pp = k - c * 49;
            dst[k] = __float2half_rn(vals[pp * VPITCH + c]);
        }
    }
}

// ============ FP16 mma.sync GEMM, split-K, BM=128 x BN=256, 8 warps x 64x64 ============
#define BM 128
#define BN 256
#define BK 32
#define HPITCH 40                 // halfs per smem row (conflict-free frag loads)
#define GSTAGES 4
#define ASZH (BM*HPITCH)
#define BSZH (BN*HPITCH)
#define STGH (ASZH+BSZH)
#define GEMM_SMEM_BYTES (GSTAGES*STGH*2)   // 122880 B

template<int KDIM, int JROWS, int JS, int SPLITK>
__global__ void __launch_bounds__(256) fcmma_kernel(
    const __half* __restrict__ A, const __half* __restrict__ Wt,
    float* __restrict__ Part)
{
    static_assert(KDIM % BK == 0, "K multiple of BK");
    constexpr int KT = KDIM / BK;
    constexpr int CH = (KT + SPLITK - 1) / SPLITK;

    extern __shared__ __half smh[];
    int tid  = threadIdx.x;
    int lane = tid & 31, wid = tid >> 5;
    int m0 = blockIdx.y * BM, n0 = blockIdx.x * BN;
    int z  = blockIdx.z;
    int t0 = z * CH;
    int ntc = min(KT - t0, CH);

    int g = lane >> 2, tg = lane & 3;
    int wm = (wid & 1) * 64;
    int wn = (wid >> 1) * 64;

    float c[4][8][4];
    #pragma unroll
    for (int mt = 0; mt < 4; mt++)
        #pragma unroll
        for (int nt = 0; nt < 8; nt++)
            #pragma unroll
            for (int q = 0; q < 4; q++) c[mt][nt][q] = 0.0f;

    int lrow = tid >> 2;     // 0..63
    int lchk = tid & 3;      // 0..3 (16B = 8-half chunks of a BK row)

    auto load_stage = [&](int s, int t) {
        __half* As = smh + s * STGH;
        __half* Bs = As + ASZH;
        int kg = t * BK + lchk * 8;
        #pragma unroll
        for (int it = 0; it < 2; it++) {
            int r = lrow + it * 64;
            cpasync16(smem_u32(As + r * HPITCH + lchk * 8),
                      A + (size_t)(m0 + r) * KDIM + kg, true);
        }
        #pragma unroll
        for (int it = 0; it < 4; it++) {
            int r = lrow + it * 64;
            int br = n0 + r;
            bool ok = ((JROWS % BN) == 0) || (br < JROWS);
            cpasync16(smem_u32(Bs + r * HPITCH + lchk * 8),
                      Wt + (size_t)(ok ? br : 0) * KDIM + kg, ok);
        }
    };

    #pragma unroll
    for (int s = 0; s < GSTAGES - 1; s++) {
        if (s < ntc) load_stage(s, t0 + s);
        asm volatile("cp.async.commit_group;" ::: "memory");
    }

    #pragma unroll 1
    for (int i = 0; i < ntc; i++) {
        asm volatile("cp.async.wait_group %0;" :: "n"(GSTAGES - 2) : "memory");
        __syncthreads();

        int tn = i + GSTAGES - 1;
        if (tn < ntc) load_stage(tn % GSTAGES, t0 + tn);
        asm volatile("cp.async.commit_group;" ::: "memory");

        const __half* As = smh + (i % GSTAGES) * STGH;
        const __half* Bs = As + ASZH;
        #pragma unroll
        for (int ks = 0; ks < 2; ks++) {
            int kk = ks * 16;
            uint32_t a[4][4], b[8][2];
            #pragma unroll
            for (int mt = 0; mt < 4; mt++) {
                int m = wm + mt * 16 + g;
                a[mt][0] = *reinterpret_cast<const uint32_t*>(As + m * HPITCH + kk + tg*2);
                a[mt][1] = *reinterpret_cast<const uint32_t*>(As + (m + 8) * HPITCH + kk + tg*2);
                a[mt][2] = *reinterpret_cast<const uint32_t*>(As + m * HPITCH + kk + tg*2 + 8);
                a[mt][3] = *reinterpret_cast<const uint32_t*>(As + (m + 8) * HPITCH + kk + tg*2 + 8);
            }
            #pragma unroll
            for (int nt = 0; nt < 8; nt++) {
                int nn = wn + nt * 8 + g;
                b[nt][0] = *reinterpret_cast<const uint32_t*>(Bs + nn * HPITCH + kk + tg*2);
                b[nt][1] = *reinterpret_cast<const uint32_t*>(Bs + nn * HPITCH + kk + tg*2 + 8);
            }
            #pragma unroll
            for (int mt = 0; mt < 4; mt++)
                #pragma unroll
                for (int nt = 0; nt < 8; nt++)
                    mma_f16(c[mt][nt], a[mt], b[nt]);
        }
    }

    float* P = Part + (size_t)z * NROI * JS;
    #pragma unroll
    for (int mt = 0; mt < 4; mt++) {
        int row0 = m0 + wm + mt * 16 + g;
        #pragma unroll
        for (int nt = 0; nt < 8; nt++) {
            int j0 = n0 + wn + nt * 8 + tg * 2;
            #pragma unroll
            for (int h = 0; h < 2; h++) {
                int row = row0 + h * 8;
                float2 v = make_float2(c[mt][nt][h*2], c[mt][nt][h*2+1]);
                *reinterpret_cast<float2*>(P + (size_t)row * JS + j0) = v;
            }
        }
    }
}

// vectorized reduce: partials + bias + relu, write fp16 for next GEMM
template<int J, int JS, int SPLITK>
__global__ void __launch_bounds__(256) reduce_half_kernel(
    const float* __restrict__ Part, const float* __restrict__ bias,
    __half* __restrict__ Cout)
{
    int idx = blockIdx.x * 256 + threadIdx.x;
    if (idx >= NROI * (J / 4)) return;
    int row = idx / (J / 4), jv = idx - row * (J / 4);
    int j = jv * 4;
    float4 v = make_float4(0.f, 0.f, 0.f, 0.f);
    #pragma unroll
    for (int z = 0; z < SPLITK; z++) {
        float4 p = *reinterpret_cast<const float4*>(Part + ((size_t)z * NROI + row) * JS + j);
        v.x += p.x; v.y += p.y; v.z += p.z; v.w += p.w;
    }
    float4 bb = *reinterpret_cast<const float4*>(bias + j);
    v.x = fmaxf(v.x + bb.x, 0.f);
    v.y = fmaxf(v.y + bb.y, 0.f);
    v.z = fmaxf(v.z + bb.z, 0.f);
    v.w = fmaxf(v.w + bb.w, 0.f);
    __half2 h0 = __floats2half2_rn(v.x, v.y);
    __half2 h1 = __floats2half2_rn(v.z, v.w);
    uint2 u;
    u.x = *reinterpret_cast<uint32_t*>(&h0);
    u.y = *reinterpret_cast<uint32_t*>(&h1);
    *reinterpret_cast<uint2*>(Cout + (size_t)row * J + j) = u;
}

// ======================= launch =======================
extern "C" void kernel_launch(void* const* d_in, const int* in_sizes, int n_in,
                              void* d_out, int out_size) {
    const float* feat = (const float*)d_in[0];
    const float* rois = (const float*)d_in[1];
    const float* w1   = (const float*)d_in[2];
    const float* b1   = (const float*)d_in[3];
    const float* w2   = (const float*)d_in[4];
    const float* b2   = (const float*)d_in[5];
    const float* w3   = (const float*)d_in[6];
    const float* b3   = (const float*)d_in[7];
    float* out = (float*)d_out;

    static __half *pXh=nullptr, *pH1h=nullptr, *pH2h=nullptr, *pw1h=nullptr, *pw2h=nullptr, *pw3h=nullptr;
    static float *pPart=nullptr;
    if (!pXh) {
        void* p;
        cudaGetSymbolAddress(&p, g_Xh);   pXh  = (__half*)p;
        cudaGetSymbolAddress(&p, g_H1h);  pH1h = (__half*)p;
        cudaGetSymbolAddress(&p, g_H2h);  pH2h = (__half*)p;
        cudaGetSymbolAddress(&p, g_w1h);  pw1h = (__half*)p;
        cudaGetSymbolAddress(&p, g_w2h);  pw2h = (__half*)p;
        cudaGetSymbolAddress(&p, g_w3h);  pw3h = (__half*)p;
        cudaGetSymbolAddress(&p, g_part); pPart = (float*)p;
        cudaFuncSetAttribute(fcmma_kernel<K1,  DFC, DFC, 9>,
                             cudaFuncAttributeMaxDynamicSharedMemorySize, GEMM_SMEM_BYTES);
        cudaFuncSetAttribute(fcmma_kernel<DFC, DFC, DFC, 8>,
                             cudaFuncAttributeMaxDynamicSharedMemorySize, GEMM_SMEM_BYTES);
        cudaFuncSetAttribute(fcmma_kernel<DFC, M3,  256, FC3_SPLITK>,
                             cudaFuncAttributeMaxDynamicSharedMemorySize, GEMM_SMEM_BYTES);
        cudaFuncSetAttribute(pool_fused_kernel<false>,
                             cudaFuncAttributeMaxDynamicSharedMemorySize, FUSED_SMEM);
        cudaFuncSetAttribute(pool_fused_kernel<true>,
                             cudaFuncAttributeMaxDynamicSharedMemorySize, FUSED_SMEM);
    }

    // 0. convert weights to fp16 (deterministic, every launch)
    cvt_half_kernel<<<(DFC*K1/4 + 255)/256, 256>>>(w1, pw1h, DFC*K1/4);
    cvt_half_kernel<<<(DFC*DFC/4 + 255)/256, 256>>>(w2, pw2h, DFC*DFC/4);
    cvt_half_kernel<<<(M3*DFC/4 + 255)/256, 256>>>(w3, pw3h, M3*DFC/4);

    // 1. NCHW -> NHWC
    dim3 tb(32, 8);
    dim3 tg((HH*WW + 31) / 32, CC / 32, NB);
    transpose_kernel<<<tg, tb>>>(feat);

    // 2. fused pool (no offsets) -> g_Xh (fp16, coalesced)
    pool_fused_kernel<false><<<NROI, 512, FUSED_SMEM>>>(rois, nullptr, nullptr, pXh);

    // 3. FC stack: split-K FP16 mma.sync (128x256, 64x64 warp tiles) + fused reduce
    fcmma_kernel<K1,  DFC, DFC, 9><<<dim3(DFC/BN, NROI/BM, 9), 256, GEMM_SMEM_BYTES>>>(pXh,  pw1h, pPart);
    reduce_half_kernel<DFC, DFC, 9><<<(NROI*DFC/4 + 255)/256, 256>>>(pPart, b1, pH1h);

    fcmma_kernel<DFC, DFC, DFC, 8><<<dim3(DFC/BN, NROI/BM, 8), 256, GEMM_SMEM_BYTES>>>(pH1h, pw2h, pPart);
    reduce_half_kernel<DFC, DFC, 8><<<(NROI*DFC/4 + 255)/256, 256>>>(pPart, b2, pH2h);

    fcmma_kernel<DFC, M3, 256, FC3_SPLITK><<<dim3(1, NROI/BM, FC3_SPLITK), 256, GEMM_SMEM_BYTES>>>(pH2h, pw3h, pPart);

    // 4. fused deformable pool: FC3 reduce + offsets + mask + gather -> out
    pool_fused_kernel<true><<<NROI, 512, FUSED_SMEM>>>(rois, pPart, b3, out);
}

// round 14
// speedup vs baseline: 2.4543x; 1.1829x over previous
#include <cuda_runtime.h>
#include <cuda_fp16.h>
#include <math.h>
#include <stdint.h>

// ---------------- problem constants ----------------
#define NB 2
#define CC 256
#define HH 100
#define WW 100
#define NROI 512
#define PP 7
#define SS 4
#define SCALEF 0.0625f
#define TRANS_STDF 0.1f
#define K1 (CC*PP*PP)     // 12544
#define DFC 1024
#define M3 (PP*PP*3)      // 147

// ---------------- scratch (device globals; no allocs allowed) ----------------
__device__ __half g_featTh[NB*HH*WW*CC];  // NHWC features, fp16 (10.2 MB)
__device__ __half g_Xh[NROI*K1];          // pooled features, fp16
__device__ __half g_H1h[NROI*DFC];
__device__ __half g_H2h[NROI*DFC];
__device__ __half g_w1h[DFC*K1];          // fp16 weights (converted per launch)
__device__ __half g_w2h[DFC*DFC];
__device__ __half g_w3h[M3*DFC];
__device__ float  g_part[9*NROI*DFC];     // split-K partials (fp32)

// ======================= small PTX helpers (sm_80+ baseline only) =======================
__device__ __forceinline__ uint32_t smem_u32(const void* p) {
    uint32_t a;
    asm("{ .reg .u64 t; cvta.to.shared.u64 t, %1; cvt.u32.u64 %0, t; }"
        : "=r"(a) : "l"(p));
    return a;
}

__device__ __forceinline__ void cpasync16(uint32_t dst, const void* src, bool pred) {
    int sz = pred ? 16 : 0;
    asm volatile("cp.async.cg.shared.global [%0], [%1], 16, %2;"
                 :: "r"(dst), "l"(src), "r"(sz) : "memory");
}

__device__ __forceinline__ void mma_f16(float c[4], const uint32_t a[4], const uint32_t b[2]) {
    asm volatile(
        "mma.sync.aligned.m16n8k16.row.col.f32.f16.f16.f32 "
        "{%0,%1,%2,%3}, {%4,%5,%6,%7}, {%8,%9}, {%0,%1,%2,%3};"
        : "+f"(c[0]), "+f"(c[1]), "+f"(c[2]), "+f"(c[3])
        : "r"(a[0]), "r"(a[1]), "r"(a[2]), "r"(a[3]), "r"(b[0]), "r"(b[1]));
}

// ---------------- fp32 -> fp16 weight conversion (per launch, deterministic) ----------------
__global__ void __launch_bounds__(256) cvt_half_kernel(const float* __restrict__ src,
                                                       __half* __restrict__ dst, int n4) {
    int i = blockIdx.x * 256 + threadIdx.x;
    if (i >= n4) return;
    float4 v = reinterpret_cast<const float4*>(src)[i];
    __half2 h0 = __floats2half2_rn(v.x, v.y);
    __half2 h1 = __floats2half2_rn(v.z, v.w);
    reinterpret_cast<__half2*>(dst)[i*2]     = h0;
    reinterpret_cast<__half2*>(dst)[i*2 + 1] = h1;
}

// ---------------- NCHW -> NHWC transpose, fp32 -> fp16 ----------------
__global__ void transpose_kernel(const float* __restrict__ feat) {
    __shared__ float tile[32][33];
    int b   = blockIdx.z;
    int hw0 = blockIdx.x * 32;
    int c0  = blockIdx.y * 32;
    int tx = threadIdx.x, ty = threadIdx.y; // (32, 8)
    const float* src = feat + (size_t)b * CC * HH * WW;
    __half* dst = g_featTh + (size_t)b * HH * WW * CC;
    #pragma unroll
    for (int j = 0; j < 32; j += 8) {
        int c  = c0 + ty + j;
        int hw = hw0 + tx;
        tile[ty + j][tx] = (hw < HH*WW) ? src[c * (HH*WW) + hw] : 0.0f;
    }
    __syncthreads();
    #pragma unroll
    for (int j = 0; j < 32; j += 8) {
        int hw = hw0 + ty + j;
        int c  = c0 + tx;
        if (hw < HH*WW) dst[hw * CC + c] = __float2half_rn(tile[tx][ty + j]);
    }
}

// ================= fused deformable PSROI pool: one block per ROI =================
// stage 0 (TRANS only): reduce FC3 split-K partials + bias -> om[147] in smem
// stage 1: threads 0..48 compute per-bin metadata (weights/mask/origin) into smem
// stage 2: 49 bins x 32 channel-octets striped over 512 threads, uint4 fp16 gathers
// stage 3: coalesced write of the 12544 row in (c*49+pp) layout (fp16 or fp32)
#define VPITCH 260
#define FC3_SPLITK 32
#define FUSED_SMEM ((49*VPITCH + 49*41 + 148) * 4)

template<bool TRANS>
__global__ void __launch_bounds__(512) pool_fused_kernel(const float* __restrict__ rois,
                                                         const float* __restrict__ Part,
                                                         const float* __restrict__ bias3,
                                                         void* __restrict__ dstbuf) {
    extern __shared__ float sg[];
    float* vals  = sg;                       // [49 pp][VPITCH], c contiguous
    float* smeta = sg + 49*VPITCH;           // [49 pp][41]
    float* som   = sg + 49*VPITCH + 49*41;   // [147] offsets+mask logits

    int n   = blockIdx.x;
    int tid = threadIdx.x;

    // ---- stage 0: fold FC3 split-K reduce into this kernel ----
    if (TRANS) {
        if (tid < M3) {
            float s = 0.0f;
            #pragma unroll
            for (int z = 0; z < FC3_SPLITK; z++)
                s += Part[((size_t)z * NROI + n) * 256 + tid];
            som[tid] = s + bias3[tid];
        }
        __syncthreads();
    }

    // ---- stage 1: metadata for 49 bins ----
    if (tid < 49) {
        int pp = tid;
        int ph = pp / 7, pw = pp % 7;
        float* wg = smeta + pp * 41;
        #pragma unroll
        for (int i = 0; i < 36; i++) wg[i] = 0.0f;

        const float* r = rois + n * 5;
        int b = (int)r[0];
        float rsw = rintf(r[1]) * SCALEF - 0.5f;
        float rsh = rintf(r[2]) * SCALEF - 0.5f;
        float rew = (rintf(r[3]) + 1.0f) * SCALEF - 0.5f;
        float reh = (rintf(r[4]) + 1.0f) * SCALEF - 0.5f;
        float roi_w = fmaxf(rew - rsw, 0.1f);
        float roi_h = fmaxf(reh - rsh, 0.1f);
        float bin_h = roi_h / (float)PP;
        float bin_w = roi_w / (float)PP;
        float sub_h = bin_h / (float)SS;
        float sub_w = bin_w / (float)SS;

        float tx_ = 0.0f, ty_ = 0.0f, mask = 1.0f;
        if (TRANS) {
            int part_h = (int)floorf((float)ph / (float)PP * 7.0f);
            int part_w = (int)floorf((float)pw / (float)PP * 7.0f);
            tx_ = som[0*49 + part_h*7 + part_w] * TRANS_STDF;
            ty_ = som[1*49 + part_h*7 + part_w] * TRANS_STDF;
            float ml = som[2*49 + pp];
            mask = 1.0f / (1.0f + expf(-ml));
        }
        float hstart = (float)ph * bin_h + rsh + ty_ * roi_h;
        float wstart = (float)pw * bin_w + rsw + tx_ * roi_w;

        int horg = (int)floorf(fminf(fmaxf(hstart, 0.0f), (float)(HH-1)));
        int worg = (int)floorf(fminf(fmaxf(wstart, 0.0f), (float)(WW-1)));
        int cnt = 0;
        #pragma unroll
        for (int iy = 0; iy < SS; iy++) {
            float h = hstart + (float)iy * sub_h;
            #pragma unroll
            for (int ix = 0; ix < SS; ix++) {
                float w = wstart + (float)ix * sub_w;
                bool valid = (w >= -0.5f) && (w <= (float)WW - 0.5f) &&
                             (h >= -0.5f) && (h <= (float)HH - 0.5f);
                if (!valid) continue;
                cnt++;
                float hc = fminf(fmaxf(h, 0.0f), (float)(HH-1));
                float wc = fminf(fmaxf(w, 0.0f), (float)(WW-1));
                int h0 = (int)floorf(hc), w0 = (int)floorf(wc);
                int h1 = min(h0 + 1, HH - 1), w1 = min(w0 + 1, WW - 1);
                float lh = hc - (float)h0, lw = wc - (float)w0;
                int r0 = min(max(h0 - horg, 0), 5);
                int r1 = min(max(h1 - horg, 0), 5);
                int c0 = min(max(w0 - worg, 0), 5);
                int c1 = min(max(w1 - worg, 0), 5);
                wg[r0*6 + c0] += (1.0f - lh) * (1.0f - lw);
                wg[r0*6 + c1] += (1.0f - lh) * lw;
                wg[r1*6 + c0] += lh * (1.0f - lw);
                wg[r1*6 + c1] += lh * lw;
            }
        }
        float invc = (cnt > 0) ? (1.0f / (float)cnt) : 0.0f;
        float scale = invc * (TRANS ? mask : 1.0f);
        #pragma unroll
        for (int i = 0; i < 36; i++) wg[i] *= scale;   // fold 1/cnt (and mask) in
        wg[38] = __int_as_float(horg);
        wg[39] = __int_as_float(worg);
        wg[40] = __int_as_float(b * HH * WW * CC);
    }
    __syncthreads();

    // ---- stage 2: gather 49 bins x 32 channel-octets (8 halfs each) ----
    #pragma unroll 1
    for (int t = tid; t < 49 * 32; t += 512) {
        int bin = t >> 5;
        int grp = t & 31;
        const float* m = smeta + bin * 41;
        int horg = __float_as_int(m[38]);
        int worg = __float_as_int(m[39]);
        int base = __float_as_int(m[40]);

        float acc[8];
        #pragma unroll
        for (int j = 0; j < 8; j++) acc[j] = 0.0f;
        #pragma unroll
        for (int cell = 0; cell < 36; cell++) {
            float wt = m[cell];
            if (wt != 0.0f) {
                int y = min(horg + cell / 6, HH - 1);
                int x = min(worg + cell % 6, WW - 1);
                uint4 f = *reinterpret_cast<const uint4*>(
                    g_featTh + base + (y * WW + x) * CC + grp * 8);
                const __half2* hp = reinterpret_cast<const __half2*>(&f);
                #pragma unroll
                for (int j = 0; j < 4; j++) {
                    float2 v = __half22float2(hp[j]);
                    acc[2*j]   += wt * v.x;
                    acc[2*j+1] += wt * v.y;
                }
            }
        }
        float* vp = vals + bin * VPITCH + grp * 8;
        #pragma unroll
        for (int j = 0; j < 8; j++) vp[j] = acc[j];
    }
    __syncthreads();

    // ---- stage 3: coalesced output in (c*49+pp) layout (guarded: K1 % 512 != 0) ----
    if (TRANS) {
        float* dst = (float*)dstbuf + (size_t)n * K1;
        #pragma unroll 1
        for (int k = tid; k < K1; k += 512) {
            int c = k / 49, pp = k - c * 49;
            dst[k] = vals[pp * VPITCH + c];
        }
    } else {
        __half* dst = (__half*)dstbuf + (size_t)n * K1;
        #pragma unroll 1
        for (int k = tid; k < K1; k += 512) {
            int c = k / 49, pp = k - c * 49;
            dst[k] = __float2half_rn(vals[pp * VPITCH + c]);
        }
    }
}

// ============ FP16 mma.sync GEMM, split-K, BM=128 x BN=256, 8 warps x 64x64 ============
#define BM 128
#define BN 256
#define BK 32
#define HPITCH 40                 // halfs per smem row (conflict-free frag loads)
#define GSTAGES 4
#define ASZH (BM*HPITCH)
#define BSZH (BN*HPITCH)
#define STGH (ASZH+BSZH)
#define GEMM_SMEM_BYTES (GSTAGES*STGH*2)   // 122880 B

template<int KDIM, int JROWS, int JS, int SPLITK>
__global__ void __launch_bounds__(256) fcmma_kernel(
    const __half* __restrict__ A, const __half* __restrict__ Wt,
    float* __restrict__ Part)
{
    static_assert(KDIM % BK == 0, "K multiple of BK");
    constexpr int KT = KDIM / BK;
    constexpr int CH = (KT + SPLITK - 1) / SPLITK;

    extern __shared__ __half smh[];
    int tid  = threadIdx.x;
    int lane = tid & 31, wid = tid >> 5;
    int m0 = blockIdx.y * BM, n0 = blockIdx.x * BN;
    int z  = blockIdx.z;
    int t0 = z * CH;
    int ntc = min(KT - t0, CH);

    int g = lane >> 2, tg = lane & 3;
    int wm = (wid & 1) * 64;
    int wn = (wid >> 1) * 64;

    float c[4][8][4];
    #pragma unroll
    for (int mt = 0; mt < 4; mt++)
        #pragma unroll
        for (int nt = 0; nt < 8; nt++)
            #pragma unroll
            for (int q = 0; q < 4; q++) c[mt][nt][q] = 0.0f;

    int lrow = tid >> 2;     // 0..63
    int lchk = tid & 3;      // 0..3 (16B = 8-half chunks of a BK row)

    auto load_stage = [&](int s, int t) {
        __half* As = smh + s * STGH;
        __half* Bs = As + ASZH;
        int kg = t * BK + lchk * 8;
        #pragma unroll
        for (int it = 0; it < 2; it++) {
            int r = lrow + it * 64;
            cpasync16(smem_u32(As + r * HPITCH + lchk * 8),
                      A + (size_t)(m0 + r) * KDIM + kg, true);
        }
        #pragma unroll
        for (int it = 0; it < 4; it++) {
            int r = lrow + it * 64;
            int br = n0 + r;
            bool ok = ((JROWS % BN) == 0) || (br < JROWS);
            cpasync16(smem_u32(Bs + r * HPITCH + lchk * 8),
                      Wt + (size_t)(ok ? br : 0) * KDIM + kg, ok);
        }
    };

    #pragma unroll
    for (int s = 0; s < GSTAGES - 1; s++) {
        if (s < ntc) load_stage(s, t0 + s);
        asm volatile("cp.async.commit_group;" ::: "memory");
    }

    #pragma unroll 1
    for (int i = 0; i < ntc; i++) {
        asm volatile("cp.async.wait_group %0;" :: "n"(GSTAGES - 2) : "memory");
        __syncthreads();

        int tn = i + GSTAGES - 1;
        if (tn < ntc) load_stage(tn % GSTAGES, t0 + tn);
        asm volatile("cp.async.commit_group;" ::: "memory");

        const __half* As = smh + (i % GSTAGES) * STGH;
        const __half* Bs = As + ASZH;
        #pragma unroll
        for (int ks = 0; ks < 2; ks++) {
            int kk = ks * 16;
            uint32_t a[4][4], b[8][2];
            #pragma unroll
            for (int mt = 0; mt < 4; mt++) {
                int m = wm + mt * 16 + g;
                a[mt][0] = *reinterpret_cast<const uint32_t*>(As + m * HPITCH + kk + tg*2);
                a[mt][1] = *reinterpret_cast<const uint32_t*>(As + (m + 8) * HPITCH + kk + tg*2);
                a[mt][2] = *reinterpret_cast<const uint32_t*>(As + m * HPITCH + kk + tg*2 + 8);
                a[mt][3] = *reinterpret_cast<const uint32_t*>(As + (m + 8) * HPITCH + kk + tg*2 + 8);
            }
            #pragma unroll
            for (int nt = 0; nt < 8; nt++) {
                int nn = wn + nt * 8 + g;
                b[nt][0] = *reinterpret_cast<const uint32_t*>(Bs + nn * HPITCH + kk + tg*2);
                b[nt][1] = *reinterpret_cast<const uint32_t*>(Bs + nn * HPITCH + kk + tg*2 + 8);
            }
            #pragma unroll
            for (int mt = 0; mt < 4; mt++)
                #pragma unroll
                for (int nt = 0; nt < 8; nt++)
                    mma_f16(c[mt][nt], a[mt], b[nt]);
        }
    }

    float* P = Part + (size_t)z * NROI * JS;
    #pragma unroll
    for (int mt = 0; mt < 4; mt++) {
        int row0 = m0 + wm + mt * 16 + g;
        #pragma unroll
        for (int nt = 0; nt < 8; nt++) {
            int j0 = n0 + wn + nt * 8 + tg * 2;
            #pragma unroll
            for (int h = 0; h < 2; h++) {
                int row = row0 + h * 8;
                float2 v = make_float2(c[mt][nt][h*2], c[mt][nt][h*2+1]);
                *reinterpret_cast<float2*>(P + (size_t)row * JS + j0) = v;
            }
        }
    }
}

// vectorized reduce: partials + bias + relu, write fp16 for next GEMM
template<int J, int JS, int SPLITK>
__global__ void __launch_bounds__(256) reduce_half_kernel(
    const float* __restrict__ Part, const float* __restrict__ bias,
    __half* __restrict__ Cout)
{
    int idx = blockIdx.x * 256 + threadIdx.x;
    if (idx >= NROI * (J / 4)) return;
    int row = idx / (J / 4), jv = idx - row * (J / 4);
    int j = jv * 4;
    float4 v = make_float4(0.f, 0.f, 0.f, 0.f);
    #pragma unroll
    for (int z = 0; z < SPLITK; z++) {
        float4 p = *reinterpret_cast<const float4*>(Part + ((size_t)z * NROI + row) * JS + j);
        v.x += p.x; v.y += p.y; v.z += p.z; v.w += p.w;
    }
    float4 bb = *reinterpret_cast<const float4*>(bias + j);
    v.x = fmaxf(v.x + bb.x, 0.f);
    v.y = fmaxf(v.y + bb.y, 0.f);
    v.z = fmaxf(v.z + bb.z, 0.f);
    v.w = fmaxf(v.w + bb.w, 0.f);
    __half2 h0 = __floats2half2_rn(v.x, v.y);
    __half2 h1 = __floats2half2_rn(v.z, v.w);
    uint2 u;
    u.x = *reinterpret_cast<uint32_t*>(&h0);
    u.y = *reinterpret_cast<uint32_t*>(&h1);
    *reinterpret_cast<uint2*>(Cout + (size_t)row * J + j) = u;
}

// ======================= launch =======================
extern "C" void kernel_launch(void* const* d_in, const int* in_sizes, int n_in,
                              void* d_out, int out_size) {
    const float* feat = (const float*)d_in[0];
    const float* rois = (const float*)d_in[1];
    const float* w1   = (const float*)d_in[2];
    const float* b1   = (const float*)d_in[3];
    const float* w2   = (const float*)d_in[4];
    const float* b2   = (const float*)d_in[5];
    const float* w3   = (const float*)d_in[6];
    const float* b3   = (const float*)d_in[7];
    float* out = (float*)d_out;

    static __half *pXh=nullptr, *pH1h=nullptr, *pH2h=nullptr, *pw1h=nullptr, *pw2h=nullptr, *pw3h=nullptr;
    static float *pPart=nullptr;
    static cudaStream_t s2 = nullptr;
    static cudaEvent_t evFork = nullptr, evJoin = nullptr;
    if (!pXh) {
        void* p;
        cudaGetSymbolAddress(&p, g_Xh);   pXh  = (__half*)p;
        cudaGetSymbolAddress(&p, g_H1h);  pH1h = (__half*)p;
        cudaGetSymbolAddress(&p, g_H2h);  pH2h = (__half*)p;
        cudaGetSymbolAddress(&p, g_w1h);  pw1h = (__half*)p;
        cudaGetSymbolAddress(&p, g_w2h);  pw2h = (__half*)p;
        cudaGetSymbolAddress(&p, g_w3h);  pw3h = (__half*)p;
        cudaGetSymbolAddress(&p, g_part); pPart = (float*)p;
        cudaFuncSetAttribute(fcmma_kernel<K1,  DFC, DFC, 9>,
                             cudaFuncAttributeMaxDynamicSharedMemorySize, GEMM_SMEM_BYTES);
        cudaFuncSetAttribute(fcmma_kernel<DFC, DFC, DFC, 8>,
                             cudaFuncAttributeMaxDynamicSharedMemorySize, GEMM_SMEM_BYTES);
        cudaFuncSetAttribute(fcmma_kernel<DFC, M3,  256, FC3_SPLITK>,
                             cudaFuncAttributeMaxDynamicSharedMemorySize, GEMM_SMEM_BYTES);
        cudaFuncSetAttribute(pool_fused_kernel<false>,
                             cudaFuncAttributeMaxDynamicSharedMemorySize, FUSED_SMEM);
        cudaFuncSetAttribute(pool_fused_kernel<true>,
                             cudaFuncAttributeMaxDynamicSharedMemorySize, FUSED_SMEM);
        cudaStreamCreateWithFlags(&s2, cudaStreamNonBlocking);
        cudaEventCreateWithFlags(&evFork, cudaEventDisableTiming);
        cudaEventCreateWithFlags(&evJoin, cudaEventDisableTiming);
    }

    // fork: weight converts on side stream, overlapped with transpose + pool1
    cudaEventRecord(evFork, 0);
    cudaStreamWaitEvent(s2, evFork, 0);
    cvt_half_kernel<<<(DFC*K1/4 + 255)/256, 256, 0, s2>>>(w1, pw1h, DFC*K1/4);
    cvt_half_kernel<<<(DFC*DFC/4 + 255)/256, 256, 0, s2>>>(w2, pw2h, DFC*DFC/4);
    cvt_half_kernel<<<(M3*DFC/4 + 255)/256, 256, 0, s2>>>(w3, pw3h, M3*DFC/4);
    cudaEventRecord(evJoin, s2);

    // main stream: NCHW -> NHWC (fp16), pool1
    dim3 tb(32, 8);
    dim3 tg((HH*WW + 31) / 32, CC / 32, NB);
    transpose_kernel<<<tg, tb>>>(feat);
    pool_fused_kernel<false><<<NROI, 512, FUSED_SMEM>>>(rois, nullptr, nullptr, pXh);

    // join: FC stack needs fp16 weights
    cudaStreamWaitEvent(0, evJoin, 0);

    fcmma_kernel<K1,  DFC, DFC, 9><<<dim3(DFC/BN, NROI/BM, 9), 256, GEMM_SMEM_BYTES>>>(pXh,  pw1h, pPart);
    reduce_half_kernel<DFC, DFC, 9><<<(NROI*DFC/4 + 255)/256, 256>>>(pPart, b1, pH1h);

    fcmma_kernel<DFC, DFC, DFC, 8><<<dim3(DFC/BN, NROI/BM, 8), 256, GEMM_SMEM_BYTES>>>(pH1h, pw2h, pPart);
    reduce_half_kernel<DFC, DFC, 8><<<(NROI*DFC/4 + 255)/256, 256>>>(pPart, b2, pH2h);

    fcmma_kernel<DFC, M3, 256, FC3_SPLITK><<<dim3(1, NROI/BM, FC3_SPLITK), 256, GEMM_SMEM_BYTES>>>(pH2h, pw3h, pPart);

    // fused deformable pool: FC3 reduce + offsets + mask + gather -> out
    pool_fused_kernel<true><<<NROI, 512, FUSED_SMEM>>>(rois, pPart, b3, out);
}

// round 15
// speedup vs baseline: 2.5920x; 1.0561x over previous
#include <cuda_runtime.h>
#include <cuda_fp16.h>
#include <math.h>
#include <stdint.h>

// ---------------- problem constants ----------------
#define NB 2
#define CC 256
#define HH 100
#define WW 100
#define NROI 512
#define PP 7
#define SS 4
#define SCALEF 0.0625f
#define TRANS_STDF 0.1f
#define K1 (CC*PP*PP)     // 12544
#define DFC 1024
#define M3 (PP*PP*3)      // 147

// ---------------- scratch (device globals; no allocs allowed) ----------------
__device__ __half g_featTh[NB*HH*WW*CC];  // NHWC features, fp16 (10.2 MB)
__device__ __half g_Xh[NROI*K1];          // pooled features, fp16
__device__ __half g_H1h[NROI*DFC];
__device__ __half g_H2h[NROI*DFC];
__device__ __half g_w1h[DFC*K1];          // fp16 weights (converted per launch)
__device__ __half g_w2h[DFC*DFC];
__device__ __half g_w3h[M3*DFC];
__device__ float  g_part[9*NROI*DFC];     // split-K partials (fp32)

// ======================= small PTX helpers (sm_80+ baseline only) =======================
__device__ __forceinline__ uint32_t smem_u32(const void* p) {
    uint32_t a;
    asm("{ .reg .u64 t; cvta.to.shared.u64 t, %1; cvt.u32.u64 %0, t; }"
        : "=r"(a) : "l"(p));
    return a;
}

__device__ __forceinline__ void cpasync16(uint32_t dst, const void* src, bool pred) {
    int sz = pred ? 16 : 0;
    asm volatile("cp.async.cg.shared.global [%0], [%1], 16, %2;"
                 :: "r"(dst), "l"(src), "r"(sz) : "memory");
}

__device__ __forceinline__ void mma_f16(float c[4], const uint32_t a[4], const uint32_t b[2]) {
    asm volatile(
        "mma.sync.aligned.m16n8k16.row.col.f32.f16.f16.f32 "
        "{%0,%1,%2,%3}, {%4,%5,%6,%7}, {%8,%9}, {%0,%1,%2,%3};"
        : "+f"(c[0]), "+f"(c[1]), "+f"(c[2]), "+f"(c[3])
        : "r"(a[0]), "r"(a[1]), "r"(a[2]), "r"(a[3]), "r"(b[0]), "r"(b[1]));
}

// ---------------- fp32 -> fp16 weight conversion (per launch, deterministic) ----------------
__global__ void __launch_bounds__(256) cvt_half_kernel(const float* __restrict__ src,
                                                       __half* __restrict__ dst, int n4) {
    int i = blockIdx.x * 256 + threadIdx.x;
    if (i >= n4) return;
    float4 v = reinterpret_cast<const float4*>(src)[i];
    __half2 h0 = __floats2half2_rn(v.x, v.y);
    __half2 h1 = __floats2half2_rn(v.z, v.w);
    reinterpret_cast<__half2*>(dst)[i*2]     = h0;
    reinterpret_cast<__half2*>(dst)[i*2 + 1] = h1;
}

// ---------------- NCHW -> NHWC transpose, fp32 -> fp16 ----------------
__global__ void transpose_kernel(const float* __restrict__ feat) {
    __shared__ float tile[32][33];
    int b   = blockIdx.z;
    int hw0 = blockIdx.x * 32;
    int c0  = blockIdx.y * 32;
    int tx = threadIdx.x, ty = threadIdx.y; // (32, 8)
    const float* src = feat + (size_t)b * CC * HH * WW;
    __half* dst = g_featTh + (size_t)b * HH * WW * CC;
    #pragma unroll
    for (int j = 0; j < 32; j += 8) {
        int c  = c0 + ty + j;
        int hw = hw0 + tx;
        tile[ty + j][tx] = (hw < HH*WW) ? src[c * (HH*WW) + hw] : 0.0f;
    }
    __syncthreads();
    #pragma unroll
    for (int j = 0; j < 32; j += 8) {
        int hw = hw0 + ty + j;
        int c  = c0 + tx;
        if (hw < HH*WW) dst[hw * CC + c] = __float2half_rn(tile[tx][ty + j]);
    }
}

// ================= fused deformable PSROI pool: one block per ROI =================
// stage 0 (TRANS only): reduce FC3 split-K partials + bias -> om[147] in smem
// stage 1: threads 0..48 compute per-bin COMPACTED cell lists (wt, feat-offset)
// stage 2: 49 bins x 32 channel-octets striped over 512 threads, uint4 fp16 gathers
// stage 3: coalesced write of the 12544 row in (c*49+pp) layout (fp16 or fp32)
#define VPITCH 260
#define MROW 56                 // per-bin meta row: [0]=nnz, then (wt, off) pairs (max 25)
#define FC3_SPLITK 32
#define FUSED_SMEM ((49*VPITCH + 49*MROW + 148) * 4)

template<bool TRANS>
__global__ void __launch_bounds__(512) pool_fused_kernel(const float* __restrict__ rois,
                                                         const float* __restrict__ Part,
                                                         const float* __restrict__ bias3,
                                                         void* __restrict__ dstbuf) {
    extern __shared__ float sg[];
    float* vals  = sg;                          // [49 pp][VPITCH]; doubles as stage-1 scratch
    float* smeta = sg + 49*VPITCH;              // [49 pp][MROW]
    float* som   = sg + 49*VPITCH + 49*MROW;    // [147] offsets+mask logits

    int n   = blockIdx.x;
    int tid = threadIdx.x;

    // ---- stage 0: fold FC3 split-K reduce into this kernel ----
    if (TRANS) {
        if (tid < M3) {
            float s = 0.0f;
            #pragma unroll
            for (int z = 0; z < FC3_SPLITK; z++)
                s += Part[((size_t)z * NROI + n) * 256 + tid];
            som[tid] = s + bias3[tid];
        }
        __syncthreads();
    }

    // ---- stage 1: metadata for 49 bins, compacted ----
    if (tid < 49) {
        int pp = tid;
        int ph = pp / 7, pw = pp % 7;
        float* wg = vals + pp * 36;      // scratch (vals not yet live)
        #pragma unroll
        for (int i = 0; i < 36; i++) wg[i] = 0.0f;

        const float* r = rois + n * 5;
        int b = (int)r[0];
        float rsw = rintf(r[1]) * SCALEF - 0.5f;
        float rsh = rintf(r[2]) * SCALEF - 0.5f;
        float rew = (rintf(r[3]) + 1.0f) * SCALEF - 0.5f;
        float reh = (rintf(r[4]) + 1.0f) * SCALEF - 0.5f;
        float roi_w = fmaxf(rew - rsw, 0.1f);
        float roi_h = fmaxf(reh - rsh, 0.1f);
        float bin_h = roi_h / (float)PP;
        float bin_w = roi_w / (float)PP;
        float sub_h = bin_h / (float)SS;
        float sub_w = bin_w / (float)SS;

        float tx_ = 0.0f, ty_ = 0.0f, mask = 1.0f;
        if (TRANS) {
            int part_h = (int)floorf((float)ph / (float)PP * 7.0f);
            int part_w = (int)floorf((float)pw / (float)PP * 7.0f);
            tx_ = som[0*49 + part_h*7 + part_w] * TRANS_STDF;
            ty_ = som[1*49 + part_h*7 + part_w] * TRANS_STDF;
            float ml = som[2*49 + pp];
            mask = 1.0f / (1.0f + expf(-ml));
        }
        float hstart = (float)ph * bin_h + rsh + ty_ * roi_h;
        float wstart = (float)pw * bin_w + rsw + tx_ * roi_w;

        int horg = (int)floorf(fminf(fmaxf(hstart, 0.0f), (float)(HH-1)));
        int worg = (int)floorf(fminf(fmaxf(wstart, 0.0f), (float)(WW-1)));
        int cnt = 0;
        #pragma unroll
        for (int iy = 0; iy < SS; iy++) {
            float h = hstart + (float)iy * sub_h;
            #pragma unroll
            for (int ix = 0; ix < SS; ix++) {
                float w = wstart + (float)ix * sub_w;
                bool valid = (w >= -0.5f) && (w <= (float)WW - 0.5f) &&
                             (h >= -0.5f) && (h <= (float)HH - 0.5f);
                if (!valid) continue;
                cnt++;
                float hc = fminf(fmaxf(h, 0.0f), (float)(HH-1));
                float wc = fminf(fmaxf(w, 0.0f), (float)(WW-1));
                int h0 = (int)floorf(hc), w0 = (int)floorf(wc);
                int h1 = min(h0 + 1, HH - 1), w1 = min(w0 + 1, WW - 1);
                float lh = hc - (float)h0, lw = wc - (float)w0;
                int r0 = min(max(h0 - horg, 0), 5);
                int r1 = min(max(h1 - horg, 0), 5);
                int c0 = min(max(w0 - worg, 0), 5);
                int c1 = min(max(w1 - worg, 0), 5);
                wg[r0*6 + c0] += (1.0f - lh) * (1.0f - lw);
                wg[r0*6 + c1] += (1.0f - lh) * lw;
                wg[r1*6 + c0] += lh * (1.0f - lw);
                wg[r1*6 + c1] += lh * lw;
            }
        }
        float invc = (cnt > 0) ? (1.0f / (float)cnt) : 0.0f;
        float scale = invc * (TRANS ? mask : 1.0f);
        int bbase = b * HH * WW;
        float* m = smeta + pp * MROW;
        int nnz = 0;
        #pragma unroll
        for (int cell = 0; cell < 36; cell++) {
            float wt = wg[cell];
            if (wt != 0.0f) {
                int y = min(horg + cell / 6, HH - 1);
                int x = min(worg + cell % 6, WW - 1);
                m[1 + 2*nnz] = wt * scale;
                m[2 + 2*nnz] = __int_as_float((bbase + y * WW + x) * CC);
                nnz++;
            }
        }
        m[0] = __int_as_float(nnz);
    }
    __syncthreads();

    // ---- stage 2: gather 49 bins x 32 channel-octets (8 halfs each) ----
    #pragma unroll 1
    for (int t = tid; t < 49 * 32; t += 512) {
        int bin = t >> 5;
        int grp = t & 31;
        const float* m = smeta + bin * MROW;
        int nnz = __float_as_int(m[0]);

        float acc[8];
        #pragma unroll
        for (int j = 0; j < 8; j++) acc[j] = 0.0f;
        #pragma unroll 1
        for (int i = 0; i < nnz; i++) {
            float wt  = m[1 + 2*i];
            int   off = __float_as_int(m[2 + 2*i]);
            uint4 f = *reinterpret_cast<const uint4*>(g_featTh + off + grp * 8);
            const __half2* hp = reinterpret_cast<const __half2*>(&f);
            #pragma unroll
            for (int j = 0; j < 4; j++) {
                float2 v = __half22float2(hp[j]);
                acc[2*j]   += wt * v.x;
                acc[2*j+1] += wt * v.y;
            }
        }
        float* vp = vals + bin * VPITCH + grp * 8;
        #pragma unroll
        for (int j = 0; j < 8; j++) vp[j] = acc[j];
    }
    __syncthreads();

    // ---- stage 3: coalesced output in (c*49+pp) layout (guarded: K1 % 512 != 0) ----
    if (TRANS) {
        float* dst = (float*)dstbuf + (size_t)n * K1;
        #pragma unroll 1
        for (int k = tid; k < K1; k += 512) {
            int c = k / 49, pp = k - c * 49;
            dst[k] = vals[pp * VPITCH + c];
        }
    } else {
        __half* dst = (__half*)dstbuf + (size_t)n * K1;
        #pragma unroll 1
        for (int k = tid; k < K1; k += 512) {
            int c = k / 49, pp = k - c * 49;
            dst[k] = __float2half_rn(vals[pp * VPITCH + c]);
        }
    }
}

// ============ FP16 mma.sync GEMM, split-K, BM=128 x BN=256, 16 warps x 32x64 ============
#define BM 128
#define BN 256
#define BK 32
#define HPITCH 40                 // halfs per smem row (conflict-free frag loads)
#define GSTAGES 4
#define ASZH (BM*HPITCH)
#define BSZH (BN*HPITCH)
#define STGH (ASZH+BSZH)
#define GEMM_SMEM_BYTES (GSTAGES*STGH*2)   // 122880 B

template<int KDIM, int JROWS, int JS, int SPLITK>
__global__ void __launch_bounds__(512) fcmma_kernel(
    const __half* __restrict__ A, const __half* __restrict__ Wt,
    float* __restrict__ Part)
{
    static_assert(KDIM % BK == 0, "K multiple of BK");
    constexpr int KT = KDIM / BK;
    constexpr int CH = (KT + SPLITK - 1) / SPLITK;

    extern __shared__ __half smh[];
    int tid  = threadIdx.x;
    int lane = tid & 31, wid = tid >> 5;   // 16 warps
    int m0 = blockIdx.y * BM, n0 = blockIdx.x * BN;
    int z  = blockIdx.z;
    int t0 = z * CH;
    int ntc = min(KT - t0, CH);

    int g = lane >> 2, tg = lane & 3;
    int wm = (wid & 3) * 32;        // 4 warps along M (32 rows each)
    int wn = (wid >> 2) * 64;       // 4 warps along N (64 cols each)

    float c[2][8][4];
    #pragma unroll
    for (int mt = 0; mt < 2; mt++)
        #pragma unroll
        for (int nt = 0; nt < 8; nt++)
            #pragma unroll
            for (int q = 0; q < 4; q++) c[mt][nt][q] = 0.0f;

    int lrow = tid >> 2;     // 0..127
    int lchk = tid & 3;      // 0..3 (16B = 8-half chunks of a BK row)

    auto load_stage = [&](int s, int t) {
        __half* As = smh + s * STGH;
        __half* Bs = As + ASZH;
        int kg = t * BK + lchk * 8;
        // A: 128 rows x 4 chunks = 512 -> exactly one per thread
        cpasync16(smem_u32(As + lrow * HPITCH + lchk * 8),
                  A + (size_t)(m0 + lrow) * KDIM + kg, true);
        // B: 256 rows -> 2 iterations
        #pragma unroll
        for (int it = 0; it < 2; it++) {
            int r = lrow + it * 128;
            int br = n0 + r;
            bool ok = ((JROWS % BN) == 0) || (br < JROWS);
            cpasync16(smem_u32(Bs + r * HPITCH + lchk * 8),
                      Wt + (size_t)(ok ? br : 0) * KDIM + kg, ok);
        }
    };

    #pragma unroll
    for (int s = 0; s < GSTAGES - 1; s++) {
        if (s < ntc) load_stage(s, t0 + s);
        asm volatile("cp.async.commit_group;" ::: "memory");
    }

    #pragma unroll 1
    for (int i = 0; i < ntc; i++) {
        asm volatile("cp.async.wait_group %0;" :: "n"(GSTAGES - 2) : "memory");
        __syncthreads();

        int tn = i + GSTAGES - 1;
        if (tn < ntc) load_stage(tn % GSTAGES, t0 + tn);
        asm volatile("cp.async.commit_group;" ::: "memory");

        const __half* As = smh + (i % GSTAGES) * STGH;
        const __half* Bs = As + ASZH;
        #pragma unroll
        for (int ks = 0; ks < 2; ks++) {
            int kk = ks * 16;
            uint32_t a[2][4], b[8][2];
            #pragma unroll
            for (int mt = 0; mt < 2; mt++) {
                int m = wm + mt * 16 + g;
                a[mt][0] = *reinterpret_cast<const uint32_t*>(As + m * HPITCH + kk + tg*2);
                a[mt][1] = *reinterpret_cast<const uint32_t*>(As + (m + 8) * HPITCH + kk + tg*2);
                a[mt][2] = *reinterpret_cast<const uint32_t*>(As + m * HPITCH + kk + tg*2 + 8);
                a[mt][3] = *reinterpret_cast<const uint32_t*>(As + (m + 8) * HPITCH + kk + tg*2 + 8);
            }
            #pragma unroll
            for (int nt = 0; nt < 8; nt++) {
                int nn = wn + nt * 8 + g;
                b[nt][0] = *reinterpret_cast<const uint32_t*>(Bs + nn * HPITCH + kk + tg*2);
                b[nt][1] = *reinterpret_cast<const uint32_t*>(Bs + nn * HPITCH + kk + tg*2 + 8);
            }
            #pragma unroll
            for (int mt = 0; mt < 2; mt++)
                #pragma unroll
                for (int nt = 0; nt < 8; nt++)
                    mma_f16(c[mt][nt], a[mt], b[nt]);
        }
    }

    float* P = Part + (size_t)z * NROI * JS;
    #pragma unroll
    for (int mt = 0; mt < 2; mt++) {
        int row0 = m0 + wm + mt * 16 + g;
        #pragma unroll
        for (int nt = 0; nt < 8; nt++) {
            int j0 = n0 + wn + nt * 8 + tg * 2;
            #pragma unroll
            for (int h = 0; h < 2; h++) {
                int row = row0 + h * 8;
                float2 v = make_float2(c[mt][nt][h*2], c[mt][nt][h*2+1]);
                *reinterpret_cast<float2*>(P + (size_t)row * JS + j0) = v;
            }
        }
    }
}

// vectorized reduce: partials + bias + relu, write fp16 for next GEMM
template<int J, int JS, int SPLITK>
__global__ void __launch_bounds__(256) reduce_half_kernel(
    const float* __restrict__ Part, const float* __restrict__ bias,
    __half* __restrict__ Cout)
{
    int idx = blockIdx.x * 256 + threadIdx.x;
    if (idx >= NROI * (J / 4)) return;
    int row = idx / (J / 4), jv = idx - row * (J / 4);
    int j = jv * 4;
    float4 v = make_float4(0.f, 0.f, 0.f, 0.f);
    #pragma unroll
    for (int z = 0; z < SPLITK; z++) {
        float4 p = *reinterpret_cast<const float4*>(Part + ((size_t)z * NROI + row) * JS + j);
        v.x += p.x; v.y += p.y; v.z += p.z; v.w += p.w;
    }
    float4 bb = *reinterpret_cast<const float4*>(bias + j);
    v.x = fmaxf(v.x + bb.x, 0.f);
    v.y = fmaxf(v.y + bb.y, 0.f);
    v.z = fmaxf(v.z + bb.z, 0.f);
    v.w = fmaxf(v.w + bb.w, 0.f);
    __half2 h0 = __floats2half2_rn(v.x, v.y);
    __half2 h1 = __floats2half2_rn(v.z, v.w);
    uint2 u;
    u.x = *reinterpret_cast<uint32_t*>(&h0);
    u.y = *reinterpret_cast<uint32_t*>(&h1);
    *reinterpret_cast<uint2*>(Cout + (size_t)row * J + j) = u;
}

// ======================= launch =======================
extern "C" void kernel_launch(void* const* d_in, const int* in_sizes, int n_in,
                              void* d_out, int out_size) {
    const float* feat = (const float*)d_in[0];
    const float* rois = (const float*)d_in[1];
    const float* w1   = (const float*)d_in[2];
    const float* b1   = (const float*)d_in[3];
    const float* w2   = (const float*)d_in[4];
    const float* b2   = (const float*)d_in[5];
    const float* w3   = (const float*)d_in[6];
    const float* b3   = (const float*)d_in[7];
    float* out = (float*)d_out;

    static __half *pXh=nullptr, *pH1h=nullptr, *pH2h=nullptr, *pw1h=nullptr, *pw2h=nullptr, *pw3h=nullptr;
    static float *pPart=nullptr;
    static cudaStream_t s2 = nullptr;
    static cudaEvent_t evFork = nullptr, evJoin = nullptr;
    if (!pXh) {
        void* p;
        cudaGetSymbolAddress(&p, g_Xh);   pXh  = (__half*)p;
        cudaGetSymbolAddress(&p, g_H1h);  pH1h = (__half*)p;
        cudaGetSymbolAddress(&p, g_H2h);  pH2h = (__half*)p;
        cudaGetSymbolAddress(&p, g_w1h);  pw1h = (__half*)p;
        cudaGetSymbolAddress(&p, g_w2h);  pw2h = (__half*)p;
        cudaGetSymbolAddress(&p, g_w3h);  pw3h = (__half*)p;
        cudaGetSymbolAddress(&p, g_part); pPart = (float*)p;
        cudaFuncSetAttribute(fcmma_kernel<K1,  DFC, DFC, 9>,
                             cudaFuncAttributeMaxDynamicSharedMemorySize, GEMM_SMEM_BYTES);
        cudaFuncSetAttribute(fcmma_kernel<DFC, DFC, DFC, 8>,
                             cudaFuncAttributeMaxDynamicSharedMemorySize, GEMM_SMEM_BYTES);
        cudaFuncSetAttribute(fcmma_kernel<DFC, M3,  256, FC3_SPLITK>,
                             cudaFuncAttributeMaxDynamicSharedMemorySize, GEMM_SMEM_BYTES);
        cudaFuncSetAttribute(pool_fused_kernel<false>,
                             cudaFuncAttributeMaxDynamicSharedMemorySize, FUSED_SMEM);
        cudaFuncSetAttribute(pool_fused_kernel<true>,
                             cudaFuncAttributeMaxDynamicSharedMemorySize, FUSED_SMEM);
        cudaStreamCreateWithFlags(&s2, cudaStreamNonBlocking);
        cudaEventCreateWithFlags(&evFork, cudaEventDisableTiming);
        cudaEventCreateWithFlags(&evJoin, cudaEventDisableTiming);
    }

    // fork: weight converts on side stream, overlapped with transpose + pool1
    cudaEventRecord(evFork, 0);
    cudaStreamWaitEvent(s2, evFork, 0);
    cvt_half_kernel<<<(DFC*K1/4 + 255)/256, 256, 0, s2>>>(w1, pw1h, DFC*K1/4);
    cvt_half_kernel<<<(DFC*DFC/4 + 255)/256, 256, 0, s2>>>(w2, pw2h, DFC*DFC/4);
    cvt_half_kernel<<<(M3*DFC/4 + 255)/256, 256, 0, s2>>>(w3, pw3h, M3*DFC/4);
    cudaEventRecord(evJoin, s2);

    // main stream: NCHW -> NHWC (fp16), pool1
    dim3 tb(32, 8);
    dim3 tg((HH*WW + 31) / 32, CC / 32, NB);
    transpose_kernel<<<tg, tb>>>(feat);
    pool_fused_kernel<false><<<NROI, 512, FUSED_SMEM>>>(rois, nullptr, nullptr, pXh);

    // join: FC stack needs fp16 weights
    cudaStreamWaitEvent(0, evJoin, 0);

    fcmma_kernel<K1,  DFC, DFC, 9><<<dim3(DFC/BN, NROI/BM, 9), 512, GEMM_SMEM_BYTES>>>(pXh,  pw1h, pPart);
    reduce_half_kernel<DFC, DFC, 9><<<(NROI*DFC/4 + 255)/256, 256>>>(pPart, b1, pH1h);

    fcmma_kernel<DFC, DFC, DFC, 8><<<dim3(DFC/BN, NROI/BM, 8), 512, GEMM_SMEM_BYTES>>>(pH1h, pw2h, pPart);
    reduce_half_kernel<DFC, DFC, 8><<<(NROI*DFC/4 + 255)/256, 256>>>(pPart, b2, pH2h);

    fcmma_kernel<DFC, M3, 256, FC3_SPLITK><<<dim3(1, NROI/BM, FC3_SPLITK), 512, GEMM_SMEM_BYTES>>>(pH2h, pw3h, pPart);

    // fused deformable pool: FC3 reduce + offsets + mask + gather -> out
    pool_fused_kernel<true><<<NROI, 512, FUSED_SMEM>>>(rois, pPart, b3, out);
}